// round 7
// baseline (speedup 1.0000x reference)
#include <cuda_runtime.h>
#include <cuda_fp16.h>
#include <math.h>
#include <stdint.h>

// ---------------- problem constants ----------------
#define TTOK   2048
#define BATCH  2
#define SEQ    1024
#define DIM    1024
#define HEADS  8
#define BH     16
#define QK_HD  128
#define V_HD   128
#define NOPE   64
#define ROPE   64
#define KV_LORA 256
#define KVA_N  320
#define KVB_N  1536
#define N_EXP  32
#define N_GROUPS 8
#define TOPK   4
#define TOPK_G 4
#define INTER  512
#define NSLOT  8192
#define EPS    1e-6f
#define ATTN_SCALE 0.08838834764831843f

typedef __half f16;

// ---------------- scratch ----------------
__device__ float g_kvF [TTOK * KVA_N];
__device__ float g_x2  [TTOK * DIM];
__device__ float g_xf  [TTOK * DIM];
__device__ float g_ybuf[NSLOT * DIM];
__device__ float g_zb  [TTOK * DIM];
__device__ float g_P   [(size_t)BH * SEQ * SEQ];

__device__ f16 g_x1h [TTOK * DIM];
__device__ f16 g_qh  [TTOK * DIM];
__device__ f16 g_cnh [TTOK * KV_LORA];
__device__ f16 g_kvph[TTOK * KVB_N];
__device__ f16 g_khh [(size_t)BH * SEQ * QK_HD];
__device__ f16 g_Ph  [(size_t)BH * SEQ * SEQ];
__device__ f16 g_attnh[TTOK * DIM];
__device__ f16 g_xfh [TTOK * DIM];
__device__ f16 g_hbufh[NSLOT * INTER];
__device__ f16 g_hsh [TTOK * INTER];

__device__ int   g_counts [N_EXP];
__device__ int   g_offsets[N_EXP];
__device__ int   g_cursor [N_EXP];
__device__ int   g_expt_idx[NSLOT];
__device__ float g_expt_w [NSLOT];
__device__ int   g_perm_token[NSLOT];
__device__ float g_perm_w   [NSLOT];
__device__ int   g_slot_of  [NSLOT];

// ---------------- helpers ----------------
__device__ __forceinline__ float blockReduceSum256(float v) {
    __shared__ float red[8];
    int lane = threadIdx.x & 31, warp = threadIdx.x >> 5;
    #pragma unroll
    for (int o = 16; o > 0; o >>= 1) v += __shfl_xor_sync(0xffffffffu, v, o);
    if (lane == 0) red[warp] = v;
    __syncthreads();
    if (warp == 0) {
        v = (lane < 8) ? red[lane] : 0.f;
        #pragma unroll
        for (int o = 4; o > 0; o >>= 1) v += __shfl_xor_sync(0xffffffffu, v, o);
        if (lane == 0) red[0] = v;
    }
    __syncthreads();
    return red[0];
}

__device__ __forceinline__ float blockReduceMax256(float v) {
    __shared__ float red[8];
    int lane = threadIdx.x & 31, warp = threadIdx.x >> 5;
    #pragma unroll
    for (int o = 16; o > 0; o >>= 1) v = fmaxf(v, __shfl_xor_sync(0xffffffffu, v, o));
    if (lane == 0) red[warp] = v;
    __syncthreads();
    if (warp == 0) {
        v = (lane < 8) ? red[lane] : -1e30f;
        #pragma unroll
        for (int o = 4; o > 0; o >>= 1) v = fmaxf(v, __shfl_xor_sync(0xffffffffu, v, o));
        if (lane == 0) red[0] = v;
    }
    __syncthreads();
    return red[0];
}

__device__ __forceinline__ void mma_f16(float* c, const uint32_t* a, const uint32_t* b) {
    asm volatile(
        "mma.sync.aligned.m16n8k16.row.col.f32.f16.f16.f32 "
        "{%0,%1,%2,%3}, {%4,%5,%6,%7}, {%8,%9}, {%0,%1,%2,%3};\n"
        : "+f"(c[0]), "+f"(c[1]), "+f"(c[2]), "+f"(c[3])
        : "r"(a[0]), "r"(a[1]), "r"(a[2]), "r"(a[3]), "r"(b[0]), "r"(b[1]));
}

__device__ __forceinline__ void ldsm_x4(uint32_t* d, uint32_t addr) {
    asm volatile("ldmatrix.sync.aligned.m8n8.x4.shared.b16 {%0,%1,%2,%3}, [%4];"
        : "=r"(d[0]), "=r"(d[1]), "=r"(d[2]), "=r"(d[3]) : "r"(addr));
}

__device__ __forceinline__ uint32_t smem_u32(const void* p) {
    uint32_t a;
    asm("{ .reg .u64 t; cvta.to.shared.u64 t, %1; cvt.u32.u64 %0, t; }"
        : "=r"(a) : "l"(p));
    return a;
}

__device__ __forceinline__ float silu_f(float a) { return a / (1.f + __expf(-a)); }

// Tile layout (both operands): 128 rows x 32 f16 = 64B rows, 4 x 16B chunks.
// Chunk swizzle: chunk ^= (row>>1)&3  -> ldmatrix phases hit 8 distinct bank groups.

// ---------------- rmsnorm (float4 vectorized) ----------------
__global__ void rmsnorm_kernel(const float* __restrict__ x, const float* __restrict__ w,
                               float* __restrict__ o32, f16* __restrict__ o16,
                               int D, int in_stride) {
    int t = blockIdx.x;
    const float4* row = (const float4*)(x + (size_t)t * in_stride);
    const float4* wv4 = (const float4*)w;
    int nv = D >> 2;
    float ss = 0.f;
    for (int i = threadIdx.x; i < nv; i += 256) {
        float4 v = row[i];
        ss += v.x * v.x + v.y * v.y + v.z * v.z + v.w * v.w;
    }
    ss = blockReduceSum256(ss);
    __shared__ float inv;
    if (threadIdx.x == 0) inv = rsqrtf(ss / (float)D + EPS);
    __syncthreads();
    float iv = inv;
    for (int i = threadIdx.x; i < nv; i += 256) {
        float4 v = row[i];
        float4 wv = wv4[i];
        float4 r = make_float4(v.x * iv * wv.x, v.y * iv * wv.y,
                               v.z * iv * wv.z, v.w * iv * wv.w);
        if (o32) *(float4*)(o32 + (size_t)t * D + i * 4) = r;
        if (o16) {
            __half2* oh = (__half2*)(o16 + (size_t)t * D + i * 4);
            oh[0] = __floats2half2_rn(r.x, r.y);
            oh[1] = __floats2half2_rn(r.z, r.w);
        }
    }
}

// ---------------- fp16 tensor-core GEMM (ldmatrix mainloop) ----------------
// MODE 0: dense; MODE 1: A rows gathered via g_perm_token (expert z);
// MODE 2: A rows at expert offset, C scaled by g_perm_w.
// BLAY: 0 = B fp32 [K][N]; 1 = B f16 [K][N]; 2 = B f16 [N][K].
// CBF: C f16 (else fp32 + optional resid in MODE 0).
// CAUSAL: 0 none; 1 = triangular tile decode; 2 = K clipped at bm+128.
template<int MODE, int BLAY, bool CBF, int CAUSAL>
__global__ void __launch_bounds__(256)
gemm_k(const f16* __restrict__ A, const void* __restrict__ Bv, void* __restrict__ Cv,
       const float* __restrict__ resid,
       int M, int N, int K, int lda, int ldb, int ldc, int zdiv,
       long long sA1, long long sA2, long long sB1, long long sB2,
       long long sC1, long long sC2) {
    __shared__ __align__(16) f16 As16[2][4096];   // 8KB per buf
    __shared__ __align__(16) f16 Bs16[2][4096];
    __shared__ int stoks[128];

    int tid = threadIdx.x;
    int warp = tid >> 5, lane = tid & 31;
    int wm = warp >> 2, wn = warp & 3;
    int m0w = wm * 64, n0w = wn * 32;

    int bn, bm;
    if (CAUSAL == 1) {
        int ti = blockIdx.x;
        int bmt = 0;
        while ((bmt + 1) * (bmt + 2) / 2 <= ti) bmt++;
        int bnt = ti - bmt * (bmt + 1) / 2;
        bm = bmt * 128; bn = bnt * 128;
    } else {
        bn = blockIdx.x * 128;
        bm = blockIdx.y * 128;
    }
    int z = blockIdx.z;
    long long offA = (long long)(z / zdiv) * sA1 + (long long)(z % zdiv) * sA2;
    long long offB = (long long)(z / zdiv) * sB1 + (long long)(z % zdiv) * sB2;
    long long offC = (long long)(z / zdiv) * sC1 + (long long)(z % zdiv) * sC2;

    int cnt = M, base = 0;
    if (MODE != 0) {
        cnt = g_counts[z];
        base = g_offsets[z];
        if (bm >= cnt) return;
    }
    if (MODE == 1) {
        if (tid < 128) stoks[tid] = (bm + tid < cnt) ? g_perm_token[base + bm + tid] : 0;
        __syncthreads();
    }

    const f16* Ap = A + offA;
    const float* Bf = (BLAY == 0) ? ((const float*)Bv + offB) : nullptr;
    const f16*  Bh = (BLAY != 0) ? ((const f16*)Bv + offB) : nullptr;

    int Keff = K;
    if (CAUSAL == 2) { int kl = bm + 128; Keff = kl < K ? kl : K; }

    float cacc[4][4][4];
    #pragma unroll
    for (int a = 0; a < 4; a++)
        #pragma unroll
        for (int b = 0; b < 4; b++)
            #pragma unroll
            for (int c = 0; c < 4; c++) cacc[a][b][c] = 0.f;

    uint4 rA[2];
    float4 rBf[4];
    uint4 rBh[2];

    char* sAc = (char*)As16;
    char* sBc = (char*)Bs16;
    uint32_t aBase = smem_u32(As16);
    uint32_t bBase = smem_u32(Bs16);

    // per-lane ldmatrix row params
    int lrl = lane & 7;
    int lb8 = (lane >> 3) & 1;
    int lhalf = lane >> 4;

    auto stage = [&](int kk) {
        #pragma unroll
        for (int i = 0; i < 2; i++) {
            int fidx = tid + i * 256;
            int r = fidx >> 2, c8 = fidx & 3;
            uint4 v = make_uint4(0, 0, 0, 0);
            if (MODE == 0) {
                int row = bm + r;
                if (row < M) v = *(const uint4*)(Ap + (size_t)row * lda + kk + c8 * 8);
            } else if (MODE == 1) {
                if (bm + r < cnt) {
                    int tok = stoks[r];
                    v = *(const uint4*)(Ap + (size_t)tok * lda + kk + c8 * 8);
                }
            } else {
                if (bm + r < cnt)
                    v = *(const uint4*)(Ap + (size_t)(base + bm + r) * lda + kk + c8 * 8);
            }
            rA[i] = v;
        }
        if (BLAY == 0) {
            #pragma unroll
            for (int i = 0; i < 4; i++) {
                int fidx = tid + i * 256;
                int r = fidx >> 5, c4 = fidx & 31;
                int col = bn + c4 * 4;
                float4 v = make_float4(0.f, 0.f, 0.f, 0.f);
                if (col < N) v = *(const float4*)(Bf + (size_t)(kk + r) * ldb + col);
                rBf[i] = v;
            }
        } else if (BLAY == 1) {
            #pragma unroll
            for (int i = 0; i < 2; i++) {
                int fidx = tid + i * 256;
                int r = fidx >> 4, c8 = fidx & 15;
                int col = bn + c8 * 8;
                uint4 v = make_uint4(0, 0, 0, 0);
                if (col < N) v = *(const uint4*)(Bh + (size_t)(kk + r) * ldb + col);
                rBh[i] = v;
            }
        } else {
            #pragma unroll
            for (int i = 0; i < 2; i++) {
                int fidx = tid + i * 256;
                int r = fidx >> 2, c8 = fidx & 3;
                uint4 v = make_uint4(0, 0, 0, 0);
                if (bn + r < N) v = *(const uint4*)(Bh + (size_t)(bn + r) * ldb + kk + c8 * 8);
                rBh[i] = v;
            }
        }
    };

    // commit: regs -> smem, both tiles in [row][k] layout w/ chunk swizzle
    auto commit = [&](int buf) {
        char* sAb = sAc + buf * 8192;
        char* sBb = sBc + buf * 8192;
        #pragma unroll
        for (int i = 0; i < 2; i++) {
            int fidx = tid + i * 256;
            int r = fidx >> 2, cb = fidx & 3;
            *(uint4*)(sAb + r * 64 + ((cb ^ ((r >> 1) & 3)) << 4)) = rA[i];
        }
        if (BLAY == 0) {
            #pragma unroll
            for (int i = 0; i < 4; i++) {
                int fidx = tid + i * 256;
                int r = fidx >> 5, c4 = fidx & 31;
                float vv[4] = {rBf[i].x, rBf[i].y, rBf[i].z, rBf[i].w};
                #pragma unroll
                for (int j = 0; j < 4; j++) {
                    int col = c4 * 4 + j;
                    f16 hv = __float2half_rn(vv[j]);
                    *(f16*)(sBb + col * 64 + ((((r >> 3) ^ ((col >> 1) & 3))) << 4) + (r & 7) * 2) = hv;
                }
            }
        } else if (BLAY == 1) {
            #pragma unroll
            for (int i = 0; i < 2; i++) {
                int fidx = tid + i * 256;
                int r = fidx >> 4, c8 = fidx & 15;
                const uint16_t* src = (const uint16_t*)&rBh[i];
                #pragma unroll
                for (int j = 0; j < 8; j++) {
                    int col = c8 * 8 + j;
                    *(uint16_t*)(sBb + col * 64 + ((((r >> 3) ^ ((col >> 1) & 3))) << 4) + (r & 7) * 2) = src[j];
                }
            }
        } else {
            #pragma unroll
            for (int i = 0; i < 2; i++) {
                int fidx = tid + i * 256;
                int r = fidx >> 2, cb = fidx & 3;
                *(uint4*)(sBb + r * 64 + ((cb ^ ((r >> 1) & 3)) << 4)) = rBh[i];
            }
        }
    };

    auto compute = [&](int buf) {
        uint32_t ab = aBase + buf * 8192;
        uint32_t bb = bBase + buf * 8192;
        #pragma unroll
        for (int ks = 0; ks < 2; ks++) {
            int kc = ks * 2;
            uint32_t afr[4][4], bfr[4][2];
            #pragma unroll
            for (int mt = 0; mt < 4; mt++) {
                int row = m0w + mt * 16 + lb8 * 8 + lrl;
                uint32_t addr = ab + row * 64 + (((kc + lhalf) ^ ((row >> 1) & 3)) << 4);
                ldsm_x4(afr[mt], addr);
            }
            #pragma unroll
            for (int ntp = 0; ntp < 4; ntp += 2) {
                int row = n0w + (ntp + lhalf) * 8 + lrl;
                uint32_t addr = bb + row * 64 + (((kc + lb8) ^ ((row >> 1) & 3)) << 4);
                uint32_t d[4];
                ldsm_x4(d, addr);
                bfr[ntp][0] = d[0]; bfr[ntp][1] = d[1];
                bfr[ntp + 1][0] = d[2]; bfr[ntp + 1][1] = d[3];
            }
            #pragma unroll
            for (int mt = 0; mt < 4; mt++)
                #pragma unroll
                for (int nt = 0; nt < 4; nt++)
                    mma_f16(cacc[mt][nt], afr[mt], bfr[nt]);
        }
    };

    stage(0);
    commit(0);
    if (Keff > 32) stage(32);
    __syncthreads();
    int buf = 0;
    for (int kk = 0; kk < Keff; kk += 32) {
        if (kk + 32 < Keff) {
            commit(buf ^ 1);
            if (kk + 64 < Keff) stage(kk + 64);
        }
        compute(buf);
        __syncthreads();
        buf ^= 1;
    }

    int g = lane >> 2, tg = lane & 3;
    float* Cf = (float*)Cv + offC;
    f16* Ch = (f16*)Cv + offC;
    #pragma unroll
    for (int mt = 0; mt < 4; mt++) {
        #pragma unroll
        for (int half_ = 0; half_ < 2; half_++) {
            int lr = bm + m0w + mt * 16 + g + half_ * 8;
            bool rowok = (MODE == 0) ? (lr < M) : (lr < cnt);
            if (!rowok) continue;
            size_t orow = (MODE == 0) ? (size_t)lr : (size_t)(base + lr);
            float scale = (MODE == 2) ? g_perm_w[base + lr] : 1.f;
            #pragma unroll
            for (int nt = 0; nt < 4; nt++) {
                int col = bn + n0w + nt * 8 + 2 * tg;
                if (col >= N) continue;
                float v0 = cacc[mt][nt][half_ * 2 + 0];
                float v1 = cacc[mt][nt][half_ * 2 + 1];
                if (MODE == 2) { v0 *= scale; v1 *= scale; }
                if (CBF) {
                    *(__half2*)(Ch + orow * ldc + col) = __floats2half2_rn(v0, v1);
                } else {
                    if (MODE == 0 && resid) {
                        float2 rv = *(const float2*)(resid + orow * ldc + col);
                        v0 += rv.x; v1 += rv.y;
                    }
                    *(float2*)(Cf + orow * ldc + col) = make_float2(v0, v1);
                }
            }
        }
    }
}

// ---------------- fused gated up-proj: C = silu(A@B1) * (A@B3), f16 out ----
// MODE 0: dense rows; MODE 1: rows gathered via g_perm_token (expert z).
template<int MODE>
__global__ void __launch_bounds__(256)
gemm_dual(const f16* __restrict__ A, const float* __restrict__ B1g,
          const float* __restrict__ B3g, f16* __restrict__ C,
          int M, int N, int K, int lda, long long strB) {
    __shared__ __align__(16) f16 As16[2][4096];
    __shared__ __align__(16) f16 B1s16[2][4096];
    __shared__ __align__(16) f16 B3s16[2][4096];
    __shared__ int stoks[128];

    int tid = threadIdx.x;
    int warp = tid >> 5, lane = tid & 31;
    int wm = warp >> 2, wn = warp & 3;
    int m0w = wm * 64, n0w = wn * 32;

    int bn = blockIdx.x * 128;
    int bm = blockIdx.y * 128;
    int z = blockIdx.z;

    int cnt = M, base = 0;
    if (MODE == 1) {
        cnt = g_counts[z];
        base = g_offsets[z];
        if (bm >= cnt) return;
        if (tid < 128) stoks[tid] = (bm + tid < cnt) ? g_perm_token[base + bm + tid] : 0;
        __syncthreads();
    }
    const float* B1 = B1g + (long long)z * strB;
    const float* B3 = B3g + (long long)z * strB;

    float acc1[4][4][4], acc3[4][4][4];
    #pragma unroll
    for (int a = 0; a < 4; a++)
        #pragma unroll
        for (int b = 0; b < 4; b++)
            #pragma unroll
            for (int c = 0; c < 4; c++) { acc1[a][b][c] = 0.f; acc3[a][b][c] = 0.f; }

    uint4 rA[2];
    float4 rB1[4], rB3[4];

    char* sAc = (char*)As16;
    char* sB1c = (char*)B1s16;
    char* sB3c = (char*)B3s16;
    uint32_t aBase = smem_u32(As16);
    uint32_t b1Base = smem_u32(B1s16);
    uint32_t b3Base = smem_u32(B3s16);

    int lrl = lane & 7;
    int lb8 = (lane >> 3) & 1;
    int lhalf = lane >> 4;

    auto stage = [&](int kk) {
        #pragma unroll
        for (int i = 0; i < 2; i++) {
            int fidx = tid + i * 256;
            int r = fidx >> 2, c8 = fidx & 3;
            uint4 v = make_uint4(0, 0, 0, 0);
            if (MODE == 0) {
                if (bm + r < M) v = *(const uint4*)(A + (size_t)(bm + r) * lda + kk + c8 * 8);
            } else {
                if (bm + r < cnt) {
                    int tok = stoks[r];
                    v = *(const uint4*)(A + (size_t)tok * lda + kk + c8 * 8);
                }
            }
            rA[i] = v;
        }
        #pragma unroll
        for (int i = 0; i < 4; i++) {
            int fidx = tid + i * 256;
            int r = fidx >> 5, c4 = fidx & 31;
            int col = bn + c4 * 4;
            float4 v1 = make_float4(0.f, 0.f, 0.f, 0.f);
            float4 v3 = v1;
            if (col < N) {
                v1 = *(const float4*)(B1 + (size_t)(kk + r) * N + col);
                v3 = *(const float4*)(B3 + (size_t)(kk + r) * N + col);
            }
            rB1[i] = v1; rB3[i] = v3;
        }
    };

    auto commit = [&](int buf) {
        char* sAb = sAc + buf * 8192;
        char* s1b = sB1c + buf * 8192;
        char* s3b = sB3c + buf * 8192;
        #pragma unroll
        for (int i = 0; i < 2; i++) {
            int fidx = tid + i * 256;
            int r = fidx >> 2, cb = fidx & 3;
            *(uint4*)(sAb + r * 64 + ((cb ^ ((r >> 1) & 3)) << 4)) = rA[i];
        }
        #pragma unroll
        for (int i = 0; i < 4; i++) {
            int fidx = tid + i * 256;
            int r = fidx >> 5, c4 = fidx & 31;
            float w1[4] = {rB1[i].x, rB1[i].y, rB1[i].z, rB1[i].w};
            float w3[4] = {rB3[i].x, rB3[i].y, rB3[i].z, rB3[i].w};
            #pragma unroll
            for (int j = 0; j < 4; j++) {
                int col = c4 * 4 + j;
                int boff = col * 64 + ((((r >> 3) ^ ((col >> 1) & 3))) << 4) + (r & 7) * 2;
                f16 h1 = __float2half_rn(w1[j]);
                f16 h3 = __float2half_rn(w3[j]);
                *(f16*)(s1b + boff) = h1;
                *(f16*)(s3b + boff) = h3;
            }
        }
    };

    auto compute = [&](int buf) {
        uint32_t ab = aBase + buf * 8192;
        uint32_t b1b = b1Base + buf * 8192;
        uint32_t b3b = b3Base + buf * 8192;
        #pragma unroll
        for (int ks = 0; ks < 2; ks++) {
            int kc = ks * 2;
            uint32_t afr[4][4], b1fr[4][2], b3fr[4][2];
            #pragma unroll
            for (int mt = 0; mt < 4; mt++) {
                int row = m0w + mt * 16 + lb8 * 8 + lrl;
                uint32_t addr = ab + row * 64 + (((kc + lhalf) ^ ((row >> 1) & 3)) << 4);
                ldsm_x4(afr[mt], addr);
            }
            #pragma unroll
            for (int ntp = 0; ntp < 4; ntp += 2) {
                int row = n0w + (ntp + lhalf) * 8 + lrl;
                uint32_t roff = row * 64 + (((kc + lb8) ^ ((row >> 1) & 3)) << 4);
                uint32_t d[4];
                ldsm_x4(d, b1b + roff);
                b1fr[ntp][0] = d[0]; b1fr[ntp][1] = d[1];
                b1fr[ntp + 1][0] = d[2]; b1fr[ntp + 1][1] = d[3];
                ldsm_x4(d, b3b + roff);
                b3fr[ntp][0] = d[0]; b3fr[ntp][1] = d[1];
                b3fr[ntp + 1][0] = d[2]; b3fr[ntp + 1][1] = d[3];
            }
            #pragma unroll
            for (int mt = 0; mt < 4; mt++)
                #pragma unroll
                for (int nt = 0; nt < 4; nt++) {
                    mma_f16(acc1[mt][nt], afr[mt], b1fr[nt]);
                    mma_f16(acc3[mt][nt], afr[mt], b3fr[nt]);
                }
        }
    };

    stage(0);
    commit(0);
    if (K > 32) stage(32);
    __syncthreads();
    int buf = 0;
    for (int kk = 0; kk < K; kk += 32) {
        if (kk + 32 < K) {
            commit(buf ^ 1);
            if (kk + 64 < K) stage(kk + 64);
        }
        compute(buf);
        __syncthreads();
        buf ^= 1;
    }

    int g = lane >> 2, tg = lane & 3;
    #pragma unroll
    for (int mt = 0; mt < 4; mt++) {
        #pragma unroll
        for (int half_ = 0; half_ < 2; half_++) {
            int lr = bm + m0w + mt * 16 + g + half_ * 8;
            bool rowok = (MODE == 0) ? (lr < M) : (lr < cnt);
            if (!rowok) continue;
            size_t orow = (MODE == 0) ? (size_t)lr : (size_t)(base + lr);
            #pragma unroll
            for (int nt = 0; nt < 4; nt++) {
                int col = bn + n0w + nt * 8 + 2 * tg;
                if (col >= N) continue;
                float a0 = acc1[mt][nt][half_ * 2 + 0];
                float a1 = acc1[mt][nt][half_ * 2 + 1];
                float b0 = acc3[mt][nt][half_ * 2 + 0];
                float b1 = acc3[mt][nt][half_ * 2 + 1];
                *(__half2*)(C + orow * N + col) =
                    __floats2half2_rn(silu_f(a0) * b0, silu_f(a1) * b1);
            }
        }
    }
}

// ---------------- pack per-head K ----------------
__global__ void prep_k_kernel(const f16* __restrict__ kvph, const float* __restrict__ kvF,
                              f16* __restrict__ kh) {
    long long i = (long long)blockIdx.x * 256 + threadIdx.x;
    if (i >= (long long)BH * SEQ * QK_HD) return;
    int d = (int)(i & 127);
    long long zs = i >> 7;
    int s = (int)(zs & (SEQ - 1));
    int zz = (int)(zs >> 10);
    int h = zz & 7, b = zz >> 3;
    size_t t = (size_t)b * SEQ + s;
    f16 val;
    if (d < NOPE) val = kvph[t * KVB_N + h * (NOPE + V_HD) + d];
    else          val = __float2half_rn(kvF[t * KVA_N + KV_LORA + (d - NOPE)]);
    kh[i] = val;
}

// ---------------- causal softmax ----------------
__global__ void softmax_kernel(const float* __restrict__ P, f16* __restrict__ Ph) {
    int r = blockIdx.x;
    long long zoff = (long long)blockIdx.y * SEQ * SEQ + (long long)r * SEQ;
    const float* row = P + zoff;
    f16* orow = Ph + zoff;
    int n = r + 1;
    int tid = threadIdx.x;
    float v[4];
    float m = -1e30f;
    #pragma unroll
    for (int j = 0; j < 4; j++) {
        int c = tid + j * 256;
        v[j] = (c < n) ? row[c] : -1e30f;
        m = fmaxf(m, v[j]);
    }
    m = blockReduceMax256(m);
    float e[4], l = 0.f;
    #pragma unroll
    for (int j = 0; j < 4; j++) {
        int c = tid + j * 256;
        e[j] = (c < n) ? __expf(ATTN_SCALE * (v[j] - m)) : 0.f;
        l += e[j];
    }
    l = blockReduceSum256(l);
    float inv = 1.f / l;
    #pragma unroll
    for (int j = 0; j < 4; j++) {
        int c = tid + j * 256;
        orow[c] = __float2half_rn(e[j] * inv);
    }
}

// ---------------- gate / routing ----------------
__global__ void zero_counts_kernel() {
    if (threadIdx.x < N_EXP) g_counts[threadIdx.x] = 0;
}

__global__ void gate_kernel(const float* __restrict__ xf, const float* __restrict__ gw,
                            const float* __restrict__ gb) {
    int t = blockIdx.x;
    __shared__ float sscore[N_EXP];
    int tid = threadIdx.x, warp = tid >> 5, lane = tid & 31;
    for (int e = warp; e < N_EXP; e += 4) {
        float s = 0.f;
        for (int d = lane; d < DIM; d += 32) s += xf[(size_t)t * DIM + d] * gw[(size_t)e * DIM + d];
        #pragma unroll
        for (int o = 16; o > 0; o >>= 1) s += __shfl_xor_sync(0xffffffffu, s, o);
        if (lane == 0) sscore[e] = 1.f / (1.f + expf(-s));
    }
    __syncthreads();
    if (tid == 0) {
        float orig[N_EXP], s[N_EXP];
        for (int e = 0; e < N_EXP; e++) { orig[e] = sscore[e]; s[e] = orig[e] + gb[e]; }
        float gs[N_GROUPS];
        for (int gg = 0; gg < N_GROUPS; gg++) {
            float m1 = -1e30f, m2 = -1e30f;
            for (int k = 0; k < 4; k++) {
                float v = s[gg * 4 + k];
                if (v > m1) { m2 = m1; m1 = v; } else if (v > m2) m2 = v;
            }
            gs[gg] = m1 + m2;
        }
        bool gsel[N_GROUPS] = {};
        for (int r = 0; r < TOPK_G; r++) {
            int best = -1; float bv = -1e30f;
            for (int gg = 0; gg < N_GROUPS; gg++)
                if (!gsel[gg] && gs[gg] > bv) { bv = gs[gg]; best = gg; }
            gsel[best] = true;
        }
        for (int gg = 0; gg < N_GROUPS; gg++)
            if (!gsel[gg]) for (int k = 0; k < 4; k++) s[gg * 4 + k] = -1e30f;
        int idx[TOPK]; bool used[N_EXP] = {};
        for (int r = 0; r < TOPK; r++) {
            int best = -1; float bv = -2e30f;
            for (int e = 0; e < N_EXP; e++)
                if (!used[e] && s[e] > bv) { bv = s[e]; best = e; }
            used[best] = true; idx[r] = best;
        }
        float wsum = 0.f;
        for (int r = 0; r < TOPK; r++) wsum += orig[idx[r]];
        float inv = 1.f / (wsum + 1e-20f);
        for (int r = 0; r < TOPK; r++) {
            g_expt_idx[t * TOPK + r] = idx[r];
            g_expt_w[t * TOPK + r] = orig[idx[r]] * inv;
            atomicAdd(&g_counts[idx[r]], 1);
        }
    }
}

__global__ void offsets_kernel() {
    if (threadIdx.x == 0) {
        int acc = 0;
        for (int e = 0; e < N_EXP; e++) {
            g_offsets[e] = acc;
            g_cursor[e] = acc;
            acc += g_counts[e];
        }
    }
}

__global__ void scatter_kernel() {
    int i = blockIdx.x * blockDim.x + threadIdx.x;
    if (i < NSLOT) {
        int e = g_expt_idx[i];
        int pos = atomicAdd(&g_cursor[e], 1);
        g_perm_token[pos] = i >> 2;
        g_perm_w[pos] = g_expt_w[i];
        g_slot_of[i] = pos;
    }
}

// ---------------- final combine ----------------
__global__ void final_kernel(float* __restrict__ out) {
    int t = blockIdx.x;
    int s0 = g_slot_of[t * 4 + 0], s1 = g_slot_of[t * 4 + 1];
    int s2 = g_slot_of[t * 4 + 2], s3 = g_slot_of[t * 4 + 3];
    for (int d = threadIdx.x; d < DIM; d += 256) {
        float v = g_x2[(size_t)t * DIM + d] + g_zb[(size_t)t * DIM + d];
        v += g_ybuf[(size_t)s0 * DIM + d];
        v += g_ybuf[(size_t)s1 * DIM + d];
        v += g_ybuf[(size_t)s2 * DIM + d];
        v += g_ybuf[(size_t)s3 * DIM + d];
        out[(size_t)t * DIM + d] = v;
    }
}

// ---------------- launcher ----------------
extern "C" void kernel_launch(void* const* d_in, const int* in_sizes, int n_in,
                              void* d_out, int out_size) {
    const float* x       = (const float*)d_in[0];
    const float* norm_a  = (const float*)d_in[1];
    const float* wq      = (const float*)d_in[2];
    const float* wkv_a   = (const float*)d_in[3];
    const float* kvnw    = (const float*)d_in[4];
    const float* wkv_b   = (const float*)d_in[5];
    const float* wo      = (const float*)d_in[6];
    const float* norm_m  = (const float*)d_in[7];
    const float* gate_w  = (const float*)d_in[8];
    const float* gate_b  = (const float*)d_in[9];
    const float* ew1     = (const float*)d_in[10];
    const float* ew2     = (const float*)d_in[11];
    const float* ew3     = (const float*)d_in[12];
    const float* sw1     = (const float*)d_in[13];
    const float* sw2     = (const float*)d_in[14];
    const float* sw3     = (const float*)d_in[15];
    float* out = (float*)d_out;

    float *kvF, *x2, *xf, *ybuf, *zb, *P;
    f16 *x1h, *qh, *cnh, *kvph, *khh, *Ph, *attnh, *xfh, *hbufh, *hsh;
    cudaGetSymbolAddress((void**)&kvF, g_kvF);
    cudaGetSymbolAddress((void**)&x2,  g_x2);
    cudaGetSymbolAddress((void**)&xf,  g_xf);
    cudaGetSymbolAddress((void**)&ybuf,g_ybuf);
    cudaGetSymbolAddress((void**)&zb,  g_zb);
    cudaGetSymbolAddress((void**)&P,   g_P);
    cudaGetSymbolAddress((void**)&x1h, g_x1h);
    cudaGetSymbolAddress((void**)&qh,  g_qh);
    cudaGetSymbolAddress((void**)&cnh, g_cnh);
    cudaGetSymbolAddress((void**)&kvph,g_kvph);
    cudaGetSymbolAddress((void**)&khh, g_khh);
    cudaGetSymbolAddress((void**)&Ph,  g_Ph);
    cudaGetSymbolAddress((void**)&attnh, g_attnh);
    cudaGetSymbolAddress((void**)&xfh, g_xfh);
    cudaGetSymbolAddress((void**)&hbufh, g_hbufh);
    cudaGetSymbolAddress((void**)&hsh, g_hsh);

    // 1) attention input norm -> fp16
    rmsnorm_kernel<<<TTOK, 256>>>(x, norm_a, nullptr, x1h, DIM, DIM);
    // 2) q = x1 @ wq
    gemm_k<0,0,true,0><<<dim3(8,16,1), 256>>>(x1h, wq, qh, nullptr,
        TTOK, DIM, DIM, DIM, DIM, DIM, 1, 0,0,0,0,0,0);
    // 3) kv = x1 @ wkv_a
    gemm_k<0,0,false,0><<<dim3(3,16,1), 256>>>(x1h, wkv_a, kvF, nullptr,
        TTOK, KVA_N, DIM, DIM, KVA_N, KVA_N, 1, 0,0,0,0,0,0);
    // 4) cn = rmsnorm(kv[:, :256])
    rmsnorm_kernel<<<TTOK, 256>>>(kvF, kvnw, nullptr, cnh, KV_LORA, KVA_N);
    // 5) kvp = cn @ wkv_b
    gemm_k<0,0,true,0><<<dim3(12,16,1), 256>>>(cnh, wkv_b, kvph, nullptr,
        TTOK, KVB_N, KV_LORA, KV_LORA, KVB_N, KVB_N, 1, 0,0,0,0,0,0);
    // 6) pack per-head K
    prep_k_kernel<<<(int)(((long long)BH*SEQ*QK_HD + 255)/256), 256>>>(kvph, kvF, khh);
    // 7) scores = q @ kh^T, lower-triangular tiles only
    gemm_k<0,2,false,1><<<dim3(36,1,BH), 256>>>(qh, khh, P, nullptr,
        SEQ, SEQ, QK_HD, DIM, QK_HD, SEQ, HEADS,
        (long long)SEQ*DIM, 128,
        (long long)HEADS*SEQ*QK_HD, (long long)SEQ*QK_HD,
        (long long)HEADS*SEQ*SEQ, (long long)SEQ*SEQ);
    // 8) causal softmax -> normalized fp16 P
    softmax_kernel<<<dim3(SEQ, BH), 256>>>(P, Ph);
    // 9) attn = P @ V with causal K-limit
    gemm_k<0,1,true,2><<<dim3(1,8,BH), 256>>>(Ph, kvph + NOPE, attnh, nullptr,
        SEQ, V_HD, SEQ, SEQ, KVB_N, DIM, HEADS,
        (long long)HEADS*SEQ*SEQ, (long long)SEQ*SEQ,
        (long long)SEQ*KVB_N, (long long)(NOPE+V_HD),
        (long long)SEQ*DIM, 128);
    // 10) x2 = x + attn @ wo
    gemm_k<0,0,false,0><<<dim3(8,16,1), 256>>>(attnh, wo, x2, x,
        TTOK, DIM, DIM, DIM, DIM, DIM, 1, 0,0,0,0,0,0);
    // 11) moe input norm
    rmsnorm_kernel<<<TTOK, 256>>>(x2, norm_m, xf, xfh, DIM, DIM);
    // 12) gate + routing
    zero_counts_kernel<<<1, 32>>>();
    gate_kernel<<<TTOK, 128>>>(xf, gate_w, gate_b);
    offsets_kernel<<<1, 32>>>();
    scatter_kernel<<<NSLOT/256, 256>>>();
    // 13) routed experts: fused gated up-proj, then weighted down-proj
    gemm_dual<1><<<dim3(4,16,N_EXP), 256>>>(xfh, ew1, ew3, hbufh,
        0, INTER, DIM, DIM, (long long)DIM*INTER);
    gemm_k<2,0,false,0><<<dim3(8,16,N_EXP), 256>>>(hbufh, ew2, ybuf, nullptr,
        0, DIM, INTER, INTER, DIM, DIM, 1, 0,0, (long long)INTER*DIM,0, 0,0);
    // 14) shared expert: fused gated up-proj, then down-proj
    gemm_dual<0><<<dim3(4,16,1), 256>>>(xfh, sw1, sw3, hsh,
        TTOK, INTER, DIM, DIM, 0);
    gemm_k<0,0,false,0><<<dim3(8,16,1), 256>>>(hsh, sw2, zb, nullptr,
        TTOK, DIM, INTER, INTER, DIM, DIM, 1, 0,0,0,0,0,0);
    // 15) final combine
    final_kernel<<<TTOK, 256>>>(out);
}

// round 8
// speedup vs baseline: 1.2383x; 1.2383x over previous
#include <cuda_runtime.h>
#include <cuda_fp16.h>
#include <math.h>
#include <stdint.h>

// ---------------- problem constants ----------------
#define TTOK   2048
#define BATCH  2
#define SEQ    1024
#define DIM    1024
#define HEADS  8
#define BH     16
#define QK_HD  128
#define V_HD   128
#define NOPE   64
#define ROPE   64
#define KV_LORA 256
#define KVA_N  320
#define KVB_N  1536
#define N_EXP  32
#define N_GROUPS 8
#define TOPK   4
#define TOPK_G 4
#define INTER  512
#define NSLOT  8192
#define EPS    1e-6f
#define ATTN_SCALE 0.08838834764831843f

typedef __half f16;

// ---------------- scratch ----------------
__device__ float g_kvF [TTOK * KVA_N];
__device__ float g_x2  [TTOK * DIM];
__device__ float g_xf  [TTOK * DIM];
__device__ float g_ybuf[NSLOT * DIM];
__device__ float g_zb  [TTOK * DIM];
__device__ float g_P   [(size_t)BH * SEQ * SEQ];

__device__ f16 g_x1h [TTOK * DIM];
__device__ f16 g_qh  [TTOK * DIM];
__device__ f16 g_cnh [TTOK * KV_LORA];
__device__ f16 g_kvph[TTOK * KVB_N];
__device__ f16 g_khh [(size_t)BH * SEQ * QK_HD];
__device__ f16 g_Ph  [(size_t)BH * SEQ * SEQ];
__device__ f16 g_attnh[TTOK * DIM];
__device__ f16 g_xfh [TTOK * DIM];
__device__ f16 g_hbufh[NSLOT * INTER];
__device__ f16 g_hsh [TTOK * INTER];

__device__ int   g_counts [N_EXP];
__device__ int   g_offsets[N_EXP];
__device__ int   g_cursor [N_EXP];
__device__ int   g_expt_idx[NSLOT];
__device__ float g_expt_w [NSLOT];
__device__ int   g_perm_token[NSLOT];
__device__ float g_perm_w   [NSLOT];
__device__ int   g_slot_of  [NSLOT];

// ---------------- helpers ----------------
__device__ __forceinline__ float blockReduceSum256(float v) {
    __shared__ float red[8];
    int lane = threadIdx.x & 31, warp = threadIdx.x >> 5;
    #pragma unroll
    for (int o = 16; o > 0; o >>= 1) v += __shfl_xor_sync(0xffffffffu, v, o);
    if (lane == 0) red[warp] = v;
    __syncthreads();
    if (warp == 0) {
        v = (lane < 8) ? red[lane] : 0.f;
        #pragma unroll
        for (int o = 4; o > 0; o >>= 1) v += __shfl_xor_sync(0xffffffffu, v, o);
        if (lane == 0) red[0] = v;
    }
    __syncthreads();
    return red[0];
}

__device__ __forceinline__ float blockReduceMax256(float v) {
    __shared__ float red[8];
    int lane = threadIdx.x & 31, warp = threadIdx.x >> 5;
    #pragma unroll
    for (int o = 16; o > 0; o >>= 1) v = fmaxf(v, __shfl_xor_sync(0xffffffffu, v, o));
    if (lane == 0) red[warp] = v;
    __syncthreads();
    if (warp == 0) {
        v = (lane < 8) ? red[lane] : -1e30f;
        #pragma unroll
        for (int o = 4; o > 0; o >>= 1) v = fmaxf(v, __shfl_xor_sync(0xffffffffu, v, o));
        if (lane == 0) red[0] = v;
    }
    __syncthreads();
    return red[0];
}

__device__ __forceinline__ void mma_f16(float* c, const uint32_t* a, const uint32_t* b) {
    asm volatile(
        "mma.sync.aligned.m16n8k16.row.col.f32.f16.f16.f32 "
        "{%0,%1,%2,%3}, {%4,%5,%6,%7}, {%8,%9}, {%0,%1,%2,%3};\n"
        : "+f"(c[0]), "+f"(c[1]), "+f"(c[2]), "+f"(c[3])
        : "r"(a[0]), "r"(a[1]), "r"(a[2]), "r"(a[3]), "r"(b[0]), "r"(b[1]));
}

__device__ __forceinline__ int swA(int row) { return ((row >> 1) & 3) << 2; }
__device__ __forceinline__ int swB(int col) { return (((col >> 1) & 3) << 2) ^ ((col >> 2) & 3); }

__device__ __forceinline__ float silu_f(float a) { return a / (1.f + __expf(-a)); }

// ---------------- rmsnorm (float4 vectorized) ----------------
__global__ void rmsnorm_kernel(const float* __restrict__ x, const float* __restrict__ w,
                               float* __restrict__ o32, f16* __restrict__ o16,
                               int D, int in_stride) {
    int t = blockIdx.x;
    const float4* row = (const float4*)(x + (size_t)t * in_stride);
    const float4* wv4 = (const float4*)w;
    int nv = D >> 2;
    float ss = 0.f;
    for (int i = threadIdx.x; i < nv; i += 256) {
        float4 v = row[i];
        ss += v.x * v.x + v.y * v.y + v.z * v.z + v.w * v.w;
    }
    ss = blockReduceSum256(ss);
    __shared__ float inv;
    if (threadIdx.x == 0) inv = rsqrtf(ss / (float)D + EPS);
    __syncthreads();
    float iv = inv;
    for (int i = threadIdx.x; i < nv; i += 256) {
        float4 v = row[i];
        float4 wv = wv4[i];
        float4 r = make_float4(v.x * iv * wv.x, v.y * iv * wv.y,
                               v.z * iv * wv.z, v.w * iv * wv.w);
        if (o32) *(float4*)(o32 + (size_t)t * D + i * 4) = r;
        if (o16) {
            __half2* oh = (__half2*)(o16 + (size_t)t * D + i * 4);
            oh[0] = __floats2half2_rn(r.x, r.y);
            oh[1] = __floats2half2_rn(r.z, r.w);
        }
    }
}

// ---------------- fp16 tensor-core GEMM (proven R4 mainloop) ----------------
// MODE 0: dense; MODE 1: A rows gathered via g_perm_token (expert z);
// MODE 2: A rows at expert offset, C scaled by g_perm_w.
// BLAY: 0 = B fp32 [K][N]; 1 = B f16 [K][N]; 2 = B f16 [N][K].
// CBF: C f16 (else fp32 + optional resid in MODE 0).
// CAUSAL: 0 none; 1 = triangular tile decode; 2 = K clipped at bm + MT*32.
// MT: warp m-tiles (4 -> 128-row CTA tile; 2 -> 64-row CTA tile).
template<int MODE, int BLAY, bool CBF, int CAUSAL, int MT>
__global__ void __launch_bounds__(256)
gemm_k(const f16* __restrict__ A, const void* __restrict__ Bv, void* __restrict__ Cv,
       const float* __restrict__ resid,
       int M, int N, int K, int lda, int ldb, int ldc, int zdiv,
       long long sA1, long long sA2, long long sB1, long long sB2,
       long long sC1, long long sC2) {
    __shared__ uint32_t As32[2][2048];
    __shared__ uint32_t Bs32[2][2048];
    __shared__ int stoks[128];

    int tid = threadIdx.x;
    int warp = tid >> 5, lane = tid & 31;
    int g = lane >> 2, tg = lane & 3;
    int wm = warp >> 2, wn = warp & 3;
    int m0w = wm * (MT * 16), n0w = wn * 32;
    const int MROWS = MT * 32;   // CTA tile rows (2 warps in m)

    int bn, bm;
    if (CAUSAL == 1) {
        int ti = blockIdx.x;
        int bmt = 0;
        while ((bmt + 1) * (bmt + 2) / 2 <= ti) bmt++;
        int bnt = ti - bmt * (bmt + 1) / 2;
        bm = bmt * 128; bn = bnt * 128;
    } else {
        bn = blockIdx.x * 128;
        bm = blockIdx.y * MROWS;
    }
    int z = blockIdx.z;
    long long offA = (long long)(z / zdiv) * sA1 + (long long)(z % zdiv) * sA2;
    long long offB = (long long)(z / zdiv) * sB1 + (long long)(z % zdiv) * sB2;
    long long offC = (long long)(z / zdiv) * sC1 + (long long)(z % zdiv) * sC2;

    int cnt = M, base = 0;
    if (MODE != 0) {
        cnt = g_counts[z];
        base = g_offsets[z];
        if (bm >= cnt) return;
    }
    if (MODE == 1) {
        if (tid < 128) stoks[tid] = (bm + tid < cnt) ? g_perm_token[base + bm + tid] : 0;
        __syncthreads();
    }

    const f16* Ap = A + offA;
    const float* Bf = (BLAY == 0) ? ((const float*)Bv + offB) : nullptr;
    const f16*  Bh = (BLAY != 0) ? ((const f16*)Bv + offB) : nullptr;

    int Keff = K;
    if (CAUSAL == 2) { int kl = bm + MROWS; Keff = kl < K ? kl : K; }

    float cacc[MT][4][4];
    #pragma unroll
    for (int a = 0; a < MT; a++)
        #pragma unroll
        for (int b = 0; b < 4; b++)
            #pragma unroll
            for (int c = 0; c < 4; c++) cacc[a][b][c] = 0.f;

    uint4 rA[MT / 2];
    float4 rBf[4];
    uint4 rBh[2];

    auto stage = [&](int kk) {
        #pragma unroll
        for (int i = 0; i < MT / 2; i++) {
            int fidx = tid + i * 256;
            int r = fidx >> 2, c8 = fidx & 3;
            uint4 v = make_uint4(0, 0, 0, 0);
            if (MODE == 0) {
                int row = bm + r;
                if (row < M) v = *(const uint4*)(Ap + (size_t)row * lda + kk + c8 * 8);
            } else if (MODE == 1) {
                if (bm + r < cnt) {
                    int tok = stoks[r];
                    v = *(const uint4*)(Ap + (size_t)tok * lda + kk + c8 * 8);
                }
            } else {
                if (bm + r < cnt)
                    v = *(const uint4*)(Ap + (size_t)(base + bm + r) * lda + kk + c8 * 8);
            }
            rA[i] = v;
        }
        if (BLAY == 0) {
            #pragma unroll
            for (int i = 0; i < 4; i++) {
                int fidx = tid + i * 256;
                int r = fidx >> 5, c4 = fidx & 31;
                int col = bn + c4 * 4;
                float4 v = make_float4(0.f, 0.f, 0.f, 0.f);
                if (col < N) v = *(const float4*)(Bf + (size_t)(kk + r) * ldb + col);
                rBf[i] = v;
            }
        } else if (BLAY == 1) {
            #pragma unroll
            for (int i = 0; i < 2; i++) {
                int fidx = tid + i * 256;
                int r = fidx >> 4, c8 = fidx & 15;
                int col = bn + c8 * 8;
                uint4 v = make_uint4(0, 0, 0, 0);
                if (col < N) v = *(const uint4*)(Bh + (size_t)(kk + r) * ldb + col);
                rBh[i] = v;
            }
        } else {
            #pragma unroll
            for (int i = 0; i < 2; i++) {
                int fidx = tid + i * 256;
                int r = fidx >> 2, c8 = fidx & 3;
                uint4 v = make_uint4(0, 0, 0, 0);
                if (bn + r < N) v = *(const uint4*)(Bh + (size_t)(bn + r) * ldb + kk + c8 * 8);
                rBh[i] = v;
            }
        }
    };

    auto commit = [&](int buf) {
        #pragma unroll
        for (int i = 0; i < MT / 2; i++) {
            int fidx = tid + i * 256;
            int r = fidx >> 2, c8 = fidx & 3;
            int slotblk = (c8 * 4) ^ swA(r);
            *(uint4*)&As32[buf][r * 16 + slotblk] = rA[i];
        }
        if (BLAY == 0) {
            uint16_t* Bs16 = (uint16_t*)Bs32[buf];
            #pragma unroll
            for (int i = 0; i < 4; i++) {
                int fidx = tid + i * 256;
                int r = fidx >> 5, c4 = fidx & 31;
                int sig = r >> 1, odd = r & 1;
                float vv[4] = {rBf[i].x, rBf[i].y, rBf[i].z, rBf[i].w};
                #pragma unroll
                for (int j = 0; j < 4; j++) {
                    int col = c4 * 4 + j;
                    f16 hv = __float2half_rn(vv[j]);
                    Bs16[col * 32 + (sig ^ swB(col)) * 2 + odd] = *(uint16_t*)&hv;
                }
            }
        } else if (BLAY == 1) {
            uint16_t* Bs16 = (uint16_t*)Bs32[buf];
            #pragma unroll
            for (int i = 0; i < 2; i++) {
                int fidx = tid + i * 256;
                int r = fidx >> 4, c8 = fidx & 15;
                int sig = r >> 1, odd = r & 1;
                const uint16_t* src = (const uint16_t*)&rBh[i];
                #pragma unroll
                for (int j = 0; j < 8; j++) {
                    int col = c8 * 8 + j;
                    Bs16[col * 32 + (sig ^ swB(col)) * 2 + odd] = src[j];
                }
            }
        } else {
            #pragma unroll
            for (int i = 0; i < 2; i++) {
                int fidx = tid + i * 256;
                int r = fidx >> 2, c8 = fidx & 3;
                int slotblk = (c8 * 4) ^ swA(r);
                *(uint4*)&Bs32[buf][r * 16 + slotblk] = rBh[i];
            }
        }
    };

    auto compute = [&](int buf) {
        #pragma unroll
        for (int ks = 0; ks < 2; ks++) {
            int sb = ks * 8;
            uint32_t afr[MT][4], bfr[4][2];
            #pragma unroll
            for (int mt = 0; mt < MT; mt++) {
                int r0 = m0w + mt * 16 + g;
                int r1 = r0 + 8;
                afr[mt][0] = As32[buf][r0 * 16 + ((sb + tg) ^ swA(r0))];
                afr[mt][1] = As32[buf][r1 * 16 + ((sb + tg) ^ swA(r1))];
                afr[mt][2] = As32[buf][r0 * 16 + ((sb + tg + 4) ^ swA(r0))];
                afr[mt][3] = As32[buf][r1 * 16 + ((sb + tg + 4) ^ swA(r1))];
            }
            #pragma unroll
            for (int nt = 0; nt < 4; nt++) {
                int c0 = n0w + nt * 8 + g;
                int sw = (BLAY == 2) ? swA(c0) : swB(c0);
                bfr[nt][0] = Bs32[buf][c0 * 16 + ((sb + tg) ^ sw)];
                bfr[nt][1] = Bs32[buf][c0 * 16 + ((sb + tg + 4) ^ sw)];
            }
            #pragma unroll
            for (int mt = 0; mt < MT; mt++)
                #pragma unroll
                for (int nt = 0; nt < 4; nt++)
                    mma_f16(cacc[mt][nt], afr[mt], bfr[nt]);
        }
    };

    stage(0);
    commit(0);
    if (Keff > 32) stage(32);
    __syncthreads();
    int buf = 0;
    for (int kk = 0; kk < Keff; kk += 32) {
        if (kk + 32 < Keff) {
            commit(buf ^ 1);
            if (kk + 64 < Keff) stage(kk + 64);
        }
        compute(buf);
        __syncthreads();
        buf ^= 1;
    }

    float* Cf = (float*)Cv + offC;
    f16* Ch = (f16*)Cv + offC;
    #pragma unroll
    for (int mt = 0; mt < MT; mt++) {
        #pragma unroll
        for (int half_ = 0; half_ < 2; half_++) {
            int lr = bm + m0w + mt * 16 + g + half_ * 8;
            bool rowok = (MODE == 0) ? (lr < M) : (lr < cnt);
            if (!rowok) continue;
            size_t orow = (MODE == 0) ? (size_t)lr : (size_t)(base + lr);
            float scale = (MODE == 2) ? g_perm_w[base + lr] : 1.f;
            #pragma unroll
            for (int nt = 0; nt < 4; nt++) {
                int col = bn + n0w + nt * 8 + 2 * tg;
                if (col >= N) continue;
                float v0 = cacc[mt][nt][half_ * 2 + 0];
                float v1 = cacc[mt][nt][half_ * 2 + 1];
                if (MODE == 2) { v0 *= scale; v1 *= scale; }
                if (CBF) {
                    *(__half2*)(Ch + orow * ldc + col) = __floats2half2_rn(v0, v1);
                } else {
                    if (MODE == 0 && resid) {
                        float2 rv = *(const float2*)(resid + orow * ldc + col);
                        v0 += rv.x; v1 += rv.y;
                    }
                    *(float2*)(Cf + orow * ldc + col) = make_float2(v0, v1);
                }
            }
        }
    }
}

// ---------------- fused gated up-proj: C = silu(A@B1) * (A@B3), f16 out ----
// MODE 0: dense rows; MODE 1: rows gathered via g_perm_token (expert z).
template<int MODE>
__global__ void __launch_bounds__(256)
gemm_dual(const f16* __restrict__ A, const float* __restrict__ B1g,
          const float* __restrict__ B3g, f16* __restrict__ C,
          int M, int N, int K, int lda, long long strB) {
    __shared__ uint32_t As32[2][2048];
    __shared__ uint32_t B1s32[2][2048];
    __shared__ uint32_t B3s32[2][2048];
    __shared__ int stoks[128];

    int tid = threadIdx.x;
    int warp = tid >> 5, lane = tid & 31;
    int g = lane >> 2, tg = lane & 3;
    int wm = warp >> 2, wn = warp & 3;
    int m0w = wm * 64, n0w = wn * 32;

    int bn = blockIdx.x * 128;
    int bm = blockIdx.y * 128;
    int z = blockIdx.z;

    int cnt = M, base = 0;
    if (MODE == 1) {
        cnt = g_counts[z];
        base = g_offsets[z];
        if (bm >= cnt) return;
        if (tid < 128) stoks[tid] = (bm + tid < cnt) ? g_perm_token[base + bm + tid] : 0;
        __syncthreads();
    }
    const float* B1 = B1g + (long long)z * strB;
    const float* B3 = B3g + (long long)z * strB;

    float acc1[4][4][4], acc3[4][4][4];
    #pragma unroll
    for (int a = 0; a < 4; a++)
        #pragma unroll
        for (int b = 0; b < 4; b++)
            #pragma unroll
            for (int c = 0; c < 4; c++) { acc1[a][b][c] = 0.f; acc3[a][b][c] = 0.f; }

    uint4 rA[2];
    float4 rB1[4], rB3[4];

    auto stage = [&](int kk) {
        #pragma unroll
        for (int i = 0; i < 2; i++) {
            int fidx = tid + i * 256;
            int r = fidx >> 2, c8 = fidx & 3;
            uint4 v = make_uint4(0, 0, 0, 0);
            if (MODE == 0) {
                if (bm + r < M) v = *(const uint4*)(A + (size_t)(bm + r) * lda + kk + c8 * 8);
            } else {
                if (bm + r < cnt) {
                    int tok = stoks[r];
                    v = *(const uint4*)(A + (size_t)tok * lda + kk + c8 * 8);
                }
            }
            rA[i] = v;
        }
        #pragma unroll
        for (int i = 0; i < 4; i++) {
            int fidx = tid + i * 256;
            int r = fidx >> 5, c4 = fidx & 31;
            int col = bn + c4 * 4;
            float4 v1 = make_float4(0.f, 0.f, 0.f, 0.f);
            float4 v3 = v1;
            if (col < N) {
                v1 = *(const float4*)(B1 + (size_t)(kk + r) * N + col);
                v3 = *(const float4*)(B3 + (size_t)(kk + r) * N + col);
            }
            rB1[i] = v1; rB3[i] = v3;
        }
    };

    auto commit = [&](int buf) {
        #pragma unroll
        for (int i = 0; i < 2; i++) {
            int fidx = tid + i * 256;
            int r = fidx >> 2, c8 = fidx & 3;
            int slotblk = (c8 * 4) ^ swA(r);
            *(uint4*)&As32[buf][r * 16 + slotblk] = rA[i];
        }
        uint16_t* b1 = (uint16_t*)B1s32[buf];
        uint16_t* b3 = (uint16_t*)B3s32[buf];
        #pragma unroll
        for (int i = 0; i < 4; i++) {
            int fidx = tid + i * 256;
            int r = fidx >> 5, c4 = fidx & 31;
            int sig = r >> 1, odd = r & 1;
            float w1[4] = {rB1[i].x, rB1[i].y, rB1[i].z, rB1[i].w};
            float w3[4] = {rB3[i].x, rB3[i].y, rB3[i].z, rB3[i].w};
            #pragma unroll
            for (int j = 0; j < 4; j++) {
                int col = c4 * 4 + j;
                int slot = (sig ^ swB(col)) * 2 + odd;
                f16 h1 = __float2half_rn(w1[j]);
                f16 h3 = __float2half_rn(w3[j]);
                b1[col * 32 + slot] = *(uint16_t*)&h1;
                b3[col * 32 + slot] = *(uint16_t*)&h3;
            }
        }
    };

    auto compute = [&](int buf) {
        #pragma unroll
        for (int ks = 0; ks < 2; ks++) {
            int sb = ks * 8;
            uint32_t afr[4][4], b1fr[4][2], b3fr[4][2];
            #pragma unroll
            for (int mt = 0; mt < 4; mt++) {
                int r0 = m0w + mt * 16 + g;
                int r1 = r0 + 8;
                afr[mt][0] = As32[buf][r0 * 16 + ((sb + tg) ^ swA(r0))];
                afr[mt][1] = As32[buf][r1 * 16 + ((sb + tg) ^ swA(r1))];
                afr[mt][2] = As32[buf][r0 * 16 + ((sb + tg + 4) ^ swA(r0))];
                afr[mt][3] = As32[buf][r1 * 16 + ((sb + tg + 4) ^ swA(r1))];
            }
            #pragma unroll
            for (int nt = 0; nt < 4; nt++) {
                int c0 = n0w + nt * 8 + g;
                int sw = swB(c0);
                b1fr[nt][0] = B1s32[buf][c0 * 16 + ((sb + tg) ^ sw)];
                b1fr[nt][1] = B1s32[buf][c0 * 16 + ((sb + tg + 4) ^ sw)];
                b3fr[nt][0] = B3s32[buf][c0 * 16 + ((sb + tg) ^ sw)];
                b3fr[nt][1] = B3s32[buf][c0 * 16 + ((sb + tg + 4) ^ sw)];
            }
            #pragma unroll
            for (int mt = 0; mt < 4; mt++)
                #pragma unroll
                for (int nt = 0; nt < 4; nt++) {
                    mma_f16(acc1[mt][nt], afr[mt], b1fr[nt]);
                    mma_f16(acc3[mt][nt], afr[mt], b3fr[nt]);
                }
        }
    };

    stage(0);
    commit(0);
    if (K > 32) stage(32);
    __syncthreads();
    int buf = 0;
    for (int kk = 0; kk < K; kk += 32) {
        if (kk + 32 < K) {
            commit(buf ^ 1);
            if (kk + 64 < K) stage(kk + 64);
        }
        compute(buf);
        __syncthreads();
        buf ^= 1;
    }

    #pragma unroll
    for (int mt = 0; mt < 4; mt++) {
        #pragma unroll
        for (int half_ = 0; half_ < 2; half_++) {
            int lr = bm + m0w + mt * 16 + g + half_ * 8;
            bool rowok = (MODE == 0) ? (lr < M) : (lr < cnt);
            if (!rowok) continue;
            size_t orow = (MODE == 0) ? (size_t)lr : (size_t)(base + lr);
            #pragma unroll
            for (int nt = 0; nt < 4; nt++) {
                int col = bn + n0w + nt * 8 + 2 * tg;
                if (col >= N) continue;
                float a0 = acc1[mt][nt][half_ * 2 + 0];
                float a1 = acc1[mt][nt][half_ * 2 + 1];
                float b0 = acc3[mt][nt][half_ * 2 + 0];
                float b1 = acc3[mt][nt][half_ * 2 + 1];
                *(__half2*)(C + orow * N + col) =
                    __floats2half2_rn(silu_f(a0) * b0, silu_f(a1) * b1);
            }
        }
    }
}

// ---------------- pack per-head K ----------------
__global__ void prep_k_kernel(const f16* __restrict__ kvph, const float* __restrict__ kvF,
                              f16* __restrict__ kh) {
    long long i = (long long)blockIdx.x * 256 + threadIdx.x;
    if (i >= (long long)BH * SEQ * QK_HD) return;
    int d = (int)(i & 127);
    long long zs = i >> 7;
    int s = (int)(zs & (SEQ - 1));
    int zz = (int)(zs >> 10);
    int h = zz & 7, b = zz >> 3;
    size_t t = (size_t)b * SEQ + s;
    f16 val;
    if (d < NOPE) val = kvph[t * KVB_N + h * (NOPE + V_HD) + d];
    else          val = __float2half_rn(kvF[t * KVA_N + KV_LORA + (d - NOPE)]);
    kh[i] = val;
}

// ---------------- causal softmax ----------------
__global__ void softmax_kernel(const float* __restrict__ P, f16* __restrict__ Ph) {
    int r = blockIdx.x;
    long long zoff = (long long)blockIdx.y * SEQ * SEQ + (long long)r * SEQ;
    const float* row = P + zoff;
    f16* orow = Ph + zoff;
    int n = r + 1;
    int tid = threadIdx.x;
    float v[4];
    float m = -1e30f;
    #pragma unroll
    for (int j = 0; j < 4; j++) {
        int c = tid + j * 256;
        v[j] = (c < n) ? row[c] : -1e30f;
        m = fmaxf(m, v[j]);
    }
    m = blockReduceMax256(m);
    float e[4], l = 0.f;
    #pragma unroll
    for (int j = 0; j < 4; j++) {
        int c = tid + j * 256;
        e[j] = (c < n) ? __expf(ATTN_SCALE * (v[j] - m)) : 0.f;
        l += e[j];
    }
    l = blockReduceSum256(l);
    float inv = 1.f / l;
    #pragma unroll
    for (int j = 0; j < 4; j++) {
        int c = tid + j * 256;
        orow[c] = __float2half_rn(e[j] * inv);
    }
}

// ---------------- gate / routing ----------------
__global__ void zero_counts_kernel() {
    if (threadIdx.x < N_EXP) g_counts[threadIdx.x] = 0;
}

__global__ void gate_kernel(const float* __restrict__ xf, const float* __restrict__ gw,
                            const float* __restrict__ gb) {
    int t = blockIdx.x;
    __shared__ float sscore[N_EXP];
    int tid = threadIdx.x, warp = tid >> 5, lane = tid & 31;
    for (int e = warp; e < N_EXP; e += 4) {
        float s = 0.f;
        for (int d = lane; d < DIM; d += 32) s += xf[(size_t)t * DIM + d] * gw[(size_t)e * DIM + d];
        #pragma unroll
        for (int o = 16; o > 0; o >>= 1) s += __shfl_xor_sync(0xffffffffu, s, o);
        if (lane == 0) sscore[e] = 1.f / (1.f + expf(-s));
    }
    __syncthreads();
    if (tid == 0) {
        float orig[N_EXP], s[N_EXP];
        for (int e = 0; e < N_EXP; e++) { orig[e] = sscore[e]; s[e] = orig[e] + gb[e]; }
        float gs[N_GROUPS];
        for (int gg = 0; gg < N_GROUPS; gg++) {
            float m1 = -1e30f, m2 = -1e30f;
            for (int k = 0; k < 4; k++) {
                float v = s[gg * 4 + k];
                if (v > m1) { m2 = m1; m1 = v; } else if (v > m2) m2 = v;
            }
            gs[gg] = m1 + m2;
        }
        bool gsel[N_GROUPS] = {};
        for (int r = 0; r < TOPK_G; r++) {
            int best = -1; float bv = -1e30f;
            for (int gg = 0; gg < N_GROUPS; gg++)
                if (!gsel[gg] && gs[gg] > bv) { bv = gs[gg]; best = gg; }
            gsel[best] = true;
        }
        for (int gg = 0; gg < N_GROUPS; gg++)
            if (!gsel[gg]) for (int k = 0; k < 4; k++) s[gg * 4 + k] = -1e30f;
        int idx[TOPK]; bool used[N_EXP] = {};
        for (int r = 0; r < TOPK; r++) {
            int best = -1; float bv = -2e30f;
            for (int e = 0; e < N_EXP; e++)
                if (!used[e] && s[e] > bv) { bv = s[e]; best = e; }
            used[best] = true; idx[r] = best;
        }
        float wsum = 0.f;
        for (int r = 0; r < TOPK; r++) wsum += orig[idx[r]];
        float inv = 1.f / (wsum + 1e-20f);
        for (int r = 0; r < TOPK; r++) {
            g_expt_idx[t * TOPK + r] = idx[r];
            g_expt_w[t * TOPK + r] = orig[idx[r]] * inv;
            atomicAdd(&g_counts[idx[r]], 1);
        }
    }
}

__global__ void offsets_kernel() {
    if (threadIdx.x == 0) {
        int acc = 0;
        for (int e = 0; e < N_EXP; e++) {
            g_offsets[e] = acc;
            g_cursor[e] = acc;
            acc += g_counts[e];
        }
    }
}

__global__ void scatter_kernel() {
    int i = blockIdx.x * blockDim.x + threadIdx.x;
    if (i < NSLOT) {
        int e = g_expt_idx[i];
        int pos = atomicAdd(&g_cursor[e], 1);
        g_perm_token[pos] = i >> 2;
        g_perm_w[pos] = g_expt_w[i];
        g_slot_of[i] = pos;
    }
}

// ---------------- final combine (float4) ----------------
__global__ void final_kernel(float* __restrict__ out) {
    int t = blockIdx.x;
    int s0 = g_slot_of[t * 4 + 0], s1 = g_slot_of[t * 4 + 1];
    int s2 = g_slot_of[t * 4 + 2], s3 = g_slot_of[t * 4 + 3];
    int i = threadIdx.x;   // DIM/4 == 256 == blockDim
    const float4* x2v = (const float4*)(g_x2 + (size_t)t * DIM);
    const float4* zbv = (const float4*)(g_zb + (size_t)t * DIM);
    const float4* y0 = (const float4*)(g_ybuf + (size_t)s0 * DIM);
    const float4* y1 = (const float4*)(g_ybuf + (size_t)s1 * DIM);
    const float4* y2 = (const float4*)(g_ybuf + (size_t)s2 * DIM);
    const float4* y3 = (const float4*)(g_ybuf + (size_t)s3 * DIM);
    float4 a = x2v[i], b = zbv[i], c0 = y0[i], c1 = y1[i], c2 = y2[i], c3 = y3[i];
    float4 r = make_float4(a.x + b.x + c0.x + c1.x + c2.x + c3.x,
                           a.y + b.y + c0.y + c1.y + c2.y + c3.y,
                           a.z + b.z + c0.z + c1.z + c2.z + c3.z,
                           a.w + b.w + c0.w + c1.w + c2.w + c3.w);
    *(float4*)(out + (size_t)t * DIM + i * 4) = r;
}

// ---------------- launcher ----------------
extern "C" void kernel_launch(void* const* d_in, const int* in_sizes, int n_in,
                              void* d_out, int out_size) {
    const float* x       = (const float*)d_in[0];
    const float* norm_a  = (const float*)d_in[1];
    const float* wq      = (const float*)d_in[2];
    const float* wkv_a   = (const float*)d_in[3];
    const float* kvnw    = (const float*)d_in[4];
    const float* wkv_b   = (const float*)d_in[5];
    const float* wo      = (const float*)d_in[6];
    const float* norm_m  = (const float*)d_in[7];
    const float* gate_w  = (const float*)d_in[8];
    const float* gate_b  = (const float*)d_in[9];
    const float* ew1     = (const float*)d_in[10];
    const float* ew2     = (const float*)d_in[11];
    const float* ew3     = (const float*)d_in[12];
    const float* sw1     = (const float*)d_in[13];
    const float* sw2     = (const float*)d_in[14];
    const float* sw3     = (const float*)d_in[15];
    float* out = (float*)d_out;

    float *kvF, *x2, *xf, *ybuf, *zb, *P;
    f16 *x1h, *qh, *cnh, *kvph, *khh, *Ph, *attnh, *xfh, *hbufh, *hsh;
    cudaGetSymbolAddress((void**)&kvF, g_kvF);
    cudaGetSymbolAddress((void**)&x2,  g_x2);
    cudaGetSymbolAddress((void**)&xf,  g_xf);
    cudaGetSymbolAddress((void**)&ybuf,g_ybuf);
    cudaGetSymbolAddress((void**)&zb,  g_zb);
    cudaGetSymbolAddress((void**)&P,   g_P);
    cudaGetSymbolAddress((void**)&x1h, g_x1h);
    cudaGetSymbolAddress((void**)&qh,  g_qh);
    cudaGetSymbolAddress((void**)&cnh, g_cnh);
    cudaGetSymbolAddress((void**)&kvph,g_kvph);
    cudaGetSymbolAddress((void**)&khh, g_khh);
    cudaGetSymbolAddress((void**)&Ph,  g_Ph);
    cudaGetSymbolAddress((void**)&attnh, g_attnh);
    cudaGetSymbolAddress((void**)&xfh, g_xfh);
    cudaGetSymbolAddress((void**)&hbufh, g_hbufh);
    cudaGetSymbolAddress((void**)&hsh, g_hsh);

    // 1) attention input norm -> fp16
    rmsnorm_kernel<<<TTOK, 256>>>(x, norm_a, nullptr, x1h, DIM, DIM);
    // 2) q = x1 @ wq
    gemm_k<0,0,true,0,4><<<dim3(8,16,1), 256>>>(x1h, wq, qh, nullptr,
        TTOK, DIM, DIM, DIM, DIM, DIM, 1, 0,0,0,0,0,0);
    // 3) kv = x1 @ wkv_a
    gemm_k<0,0,false,0,4><<<dim3(3,16,1), 256>>>(x1h, wkv_a, kvF, nullptr,
        TTOK, KVA_N, DIM, DIM, KVA_N, KVA_N, 1, 0,0,0,0,0,0);
    // 4) cn = rmsnorm(kv[:, :256])
    rmsnorm_kernel<<<TTOK, 256>>>(kvF, kvnw, nullptr, cnh, KV_LORA, KVA_N);
    // 5) kvp = cn @ wkv_b
    gemm_k<0,0,true,0,4><<<dim3(12,16,1), 256>>>(cnh, wkv_b, kvph, nullptr,
        TTOK, KVB_N, KV_LORA, KV_LORA, KVB_N, KVB_N, 1, 0,0,0,0,0,0);
    // 6) pack per-head K
    prep_k_kernel<<<(int)(((long long)BH*SEQ*QK_HD + 255)/256), 256>>>(kvph, kvF, khh);
    // 7) scores = q @ kh^T, lower-triangular tiles only
    gemm_k<0,2,false,1,4><<<dim3(36,1,BH), 256>>>(qh, khh, P, nullptr,
        SEQ, SEQ, QK_HD, DIM, QK_HD, SEQ, HEADS,
        (long long)SEQ*DIM, 128,
        (long long)HEADS*SEQ*QK_HD, (long long)SEQ*QK_HD,
        (long long)HEADS*SEQ*SEQ, (long long)SEQ*SEQ);
    // 8) causal softmax -> normalized fp16 P
    softmax_kernel<<<dim3(SEQ, BH), 256>>>(P, Ph);
    // 9) attn = P @ V, 64-row tiles (MT=2) for 2x CTA occupancy, causal K-limit
    gemm_k<0,1,true,2,2><<<dim3(1,16,BH), 256>>>(Ph, kvph + NOPE, attnh, nullptr,
        SEQ, V_HD, SEQ, SEQ, KVB_N, DIM, HEADS,
        (long long)HEADS*SEQ*SEQ, (long long)SEQ*SEQ,
        (long long)SEQ*KVB_N, (long long)(NOPE+V_HD),
        (long long)SEQ*DIM, 128);
    // 10) x2 = x + attn @ wo
    gemm_k<0,0,false,0,4><<<dim3(8,16,1), 256>>>(attnh, wo, x2, x,
        TTOK, DIM, DIM, DIM, DIM, DIM, 1, 0,0,0,0,0,0);
    // 11) moe input norm
    rmsnorm_kernel<<<TTOK, 256>>>(x2, norm_m, xf, xfh, DIM, DIM);
    // 12) gate + routing
    zero_counts_kernel<<<1, 32>>>();
    gate_kernel<<<TTOK, 128>>>(xf, gate_w, gate_b);
    offsets_kernel<<<1, 32>>>();
    scatter_kernel<<<NSLOT/256, 256>>>();
    // 13) routed experts: fused gated up-proj, then weighted down-proj
    gemm_dual<1><<<dim3(4,16,N_EXP), 256>>>(xfh, ew1, ew3, hbufh,
        0, INTER, DIM, DIM, (long long)DIM*INTER);
    gemm_k<2,0,false,0,4><<<dim3(8,16,N_EXP), 256>>>(hbufh, ew2, ybuf, nullptr,
        0, DIM, INTER, INTER, DIM, DIM, 1, 0,0, (long long)INTER*DIM,0, 0,0);
    // 14) shared expert: fused gated up-proj, then down-proj
    gemm_dual<0><<<dim3(4,16,1), 256>>>(xfh, sw1, sw3, hsh,
        TTOK, INTER, DIM, DIM, 0);
    gemm_k<0,0,false,0,4><<<dim3(8,16,1), 256>>>(hsh, sw2, zb, nullptr,
        TTOK, DIM, INTER, INTER, DIM, DIM, 1, 0,0,0,0,0,0);
    // 15) final combine
    final_kernel<<<TTOK, 256>>>(out);
}

// round 9
// speedup vs baseline: 1.5907x; 1.2845x over previous
#include <cuda_runtime.h>
#include <cuda_fp16.h>
#include <math.h>
#include <stdint.h>

// ---------------- problem constants ----------------
#define TTOK   2048
#define BATCH  2
#define SEQ    1024
#define DIM    1024
#define HEADS  8
#define BH     16
#define QK_HD  128
#define V_HD   128
#define NOPE   64
#define ROPE   64
#define KV_LORA 256
#define KVA_N  320
#define KVB_N  1536
#define N_EXP  32
#define N_GROUPS 8
#define TOPK   4
#define TOPK_G 4
#define INTER  512
#define NSLOT  8192
#define EPS    1e-6f
#define ATTN_SCALE 0.08838834764831843f

typedef __half f16;

// ---------------- scratch ----------------
__device__ float g_kvF [TTOK * KVA_N];
__device__ float g_x2  [TTOK * DIM];
__device__ float g_xf  [TTOK * DIM];
__device__ float g_ybuf[NSLOT * DIM];
__device__ float g_zb  [TTOK * DIM];
__device__ float g_P   [(size_t)BH * SEQ * SEQ];

__device__ f16 g_x1h [TTOK * DIM];
__device__ f16 g_qh  [TTOK * DIM];
__device__ f16 g_cnh [TTOK * KV_LORA];
__device__ f16 g_kvph[TTOK * KVB_N];
__device__ f16 g_khh [(size_t)BH * SEQ * QK_HD];
__device__ f16 g_Ph  [(size_t)BH * SEQ * SEQ];
__device__ f16 g_attnh[TTOK * DIM];
__device__ f16 g_xfh [TTOK * DIM];
__device__ f16 g_hbufh[NSLOT * INTER];
__device__ f16 g_hsh [TTOK * INTER];

__device__ int   g_counts [N_EXP];
__device__ int   g_offsets[N_EXP];
__device__ int   g_cursor [N_EXP];
__device__ int   g_expt_idx[NSLOT];
__device__ float g_expt_w [NSLOT];
__device__ int   g_perm_token[NSLOT];
__device__ float g_perm_w   [NSLOT];
__device__ int   g_slot_of  [NSLOT];

// ---------------- helpers ----------------
__device__ __forceinline__ float blockReduceSum256(float v) {
    __shared__ float red[8];
    int lane = threadIdx.x & 31, warp = threadIdx.x >> 5;
    #pragma unroll
    for (int o = 16; o > 0; o >>= 1) v += __shfl_xor_sync(0xffffffffu, v, o);
    if (lane == 0) red[warp] = v;
    __syncthreads();
    if (warp == 0) {
        v = (lane < 8) ? red[lane] : 0.f;
        #pragma unroll
        for (int o = 4; o > 0; o >>= 1) v += __shfl_xor_sync(0xffffffffu, v, o);
        if (lane == 0) red[0] = v;
    }
    __syncthreads();
    return red[0];
}

__device__ __forceinline__ float blockReduceMax256(float v) {
    __shared__ float red[8];
    int lane = threadIdx.x & 31, warp = threadIdx.x >> 5;
    #pragma unroll
    for (int o = 16; o > 0; o >>= 1) v = fmaxf(v, __shfl_xor_sync(0xffffffffu, v, o));
    if (lane == 0) red[warp] = v;
    __syncthreads();
    if (warp == 0) {
        v = (lane < 8) ? red[lane] : -1e30f;
        #pragma unroll
        for (int o = 4; o > 0; o >>= 1) v = fmaxf(v, __shfl_xor_sync(0xffffffffu, v, o));
        if (lane == 0) red[0] = v;
    }
    __syncthreads();
    return red[0];
}

__device__ __forceinline__ void mma_f16(float* c, const uint32_t* a, const uint32_t* b) {
    asm volatile(
        "mma.sync.aligned.m16n8k16.row.col.f32.f16.f16.f32 "
        "{%0,%1,%2,%3}, {%4,%5,%6,%7}, {%8,%9}, {%0,%1,%2,%3};\n"
        : "+f"(c[0]), "+f"(c[1]), "+f"(c[2]), "+f"(c[3])
        : "r"(a[0]), "r"(a[1]), "r"(a[2]), "r"(a[3]), "r"(b[0]), "r"(b[1]));
}

__device__ __forceinline__ int swA(int row) { return ((row >> 1) & 3) << 2; }
__device__ __forceinline__ int swB(int col) { return (((col >> 1) & 3) << 2) ^ ((col >> 2) & 3); }

__device__ __forceinline__ float silu_f(float a) { return a / (1.f + __expf(-a)); }

// ---------------- rmsnorm (float4 vectorized) ----------------
__global__ void rmsnorm_kernel(const float* __restrict__ x, const float* __restrict__ w,
                               float* __restrict__ o32, f16* __restrict__ o16,
                               int D, int in_stride) {
    int t = blockIdx.x;
    const float4* row = (const float4*)(x + (size_t)t * in_stride);
    const float4* wv4 = (const float4*)w;
    int nv = D >> 2;
    float ss = 0.f;
    for (int i = threadIdx.x; i < nv; i += 256) {
        float4 v = row[i];
        ss += v.x * v.x + v.y * v.y + v.z * v.z + v.w * v.w;
    }
    ss = blockReduceSum256(ss);
    __shared__ float inv;
    if (threadIdx.x == 0) inv = rsqrtf(ss / (float)D + EPS);
    __syncthreads();
    float iv = inv;
    for (int i = threadIdx.x; i < nv; i += 256) {
        float4 v = row[i];
        float4 wv = wv4[i];
        float4 r = make_float4(v.x * iv * wv.x, v.y * iv * wv.y,
                               v.z * iv * wv.z, v.w * iv * wv.w);
        if (o32) *(float4*)(o32 + (size_t)t * D + i * 4) = r;
        if (o16) {
            __half2* oh = (__half2*)(o16 + (size_t)t * D + i * 4);
            oh[0] = __floats2half2_rn(r.x, r.y);
            oh[1] = __floats2half2_rn(r.z, r.w);
        }
    }
}

// ---------------- fp16 tensor-core GEMM -----------------------------------
// CTA tile: 128 x (WN*32). 8 warps as (8/WN) x WN; per-warp WN m-subtiles x 4 n-subtiles.
// WN=4 reproduces the proven 128x128 config bit-for-bit; WN=2 gives 128x64.
// MODE 0: dense; MODE 1: A rows gathered via g_perm_token (expert z);
// MODE 2: A rows at expert offset, C scaled by g_perm_w.
// BLAY: 0 = B fp32 [K][N]; 1 = B f16 [K][N]; 2 = B f16 [N][K].
// CBF: C f16 (else fp32 + optional resid in MODE 0).
// CAUSAL: 0 none; 1 = triangular tile decode (WN=4 only); 2 = K clipped at bm+128.
template<int MODE, int BLAY, bool CBF, int CAUSAL, int WN>
__global__ void __launch_bounds__(256)
gemm_k(const f16* __restrict__ A, const void* __restrict__ Bv, void* __restrict__ Cv,
       const float* __restrict__ resid,
       int M, int N, int K, int lda, int ldb, int ldc, int zdiv,
       long long sA1, long long sA2, long long sB1, long long sB2,
       long long sC1, long long sC2) {
    const int NCOLS = WN * 32;
    __shared__ uint32_t As32[2][2048];
    __shared__ uint32_t Bs32[2][WN * 512];
    __shared__ int stoks[128];

    int tid = threadIdx.x;
    int warp = tid >> 5, lane = tid & 31;
    int g = lane >> 2, tg = lane & 3;
    int wm = warp / WN, wn = warp % WN;
    int m0w = wm * (WN * 16), n0w = wn * 32;

    int bn, bm;
    if (CAUSAL == 1) {
        int ti = blockIdx.x;
        int bmt = 0;
        while ((bmt + 1) * (bmt + 2) / 2 <= ti) bmt++;
        int bnt = ti - bmt * (bmt + 1) / 2;
        bm = bmt * 128; bn = bnt * 128;
    } else {
        bn = blockIdx.x * NCOLS;
        bm = blockIdx.y * 128;
    }
    int z = blockIdx.z;
    long long offA = (long long)(z / zdiv) * sA1 + (long long)(z % zdiv) * sA2;
    long long offB = (long long)(z / zdiv) * sB1 + (long long)(z % zdiv) * sB2;
    long long offC = (long long)(z / zdiv) * sC1 + (long long)(z % zdiv) * sC2;

    int cnt = M, base = 0;
    if (MODE != 0) {
        cnt = g_counts[z];
        base = g_offsets[z];
        if (bm >= cnt) return;
    }
    if (MODE == 1) {
        if (tid < 128) stoks[tid] = (bm + tid < cnt) ? g_perm_token[base + bm + tid] : 0;
        __syncthreads();
    }

    const f16* Ap = A + offA;
    const float* Bf = (BLAY == 0) ? ((const float*)Bv + offB) : nullptr;
    const f16*  Bh = (BLAY != 0) ? ((const f16*)Bv + offB) : nullptr;

    int Keff = K;
    if (CAUSAL == 2) { int kl = bm + 128; Keff = kl < K ? kl : K; }

    float cacc[WN][4][4];
    #pragma unroll
    for (int a = 0; a < WN; a++)
        #pragma unroll
        for (int b = 0; b < 4; b++)
            #pragma unroll
            for (int c = 0; c < 4; c++) cacc[a][b][c] = 0.f;

    uint4 rA[2];
    float4 rBf[WN];
    uint4 rBh[WN / 2];

    auto stage = [&](int kk) {
        #pragma unroll
        for (int i = 0; i < 2; i++) {
            int fidx = tid + i * 256;
            int r = fidx >> 2, c8 = fidx & 3;
            uint4 v = make_uint4(0, 0, 0, 0);
            if (MODE == 0) {
                int row = bm + r;
                if (row < M) v = *(const uint4*)(Ap + (size_t)row * lda + kk + c8 * 8);
            } else if (MODE == 1) {
                if (bm + r < cnt) {
                    int tok = stoks[r];
                    v = *(const uint4*)(Ap + (size_t)tok * lda + kk + c8 * 8);
                }
            } else {
                if (bm + r < cnt)
                    v = *(const uint4*)(Ap + (size_t)(base + bm + r) * lda + kk + c8 * 8);
            }
            rA[i] = v;
        }
        if (BLAY == 0) {
            #pragma unroll
            for (int i = 0; i < WN; i++) {
                int fidx = tid + i * 256;
                int r = fidx / (NCOLS / 4), c4 = fidx % (NCOLS / 4);
                int col = bn + c4 * 4;
                float4 v = make_float4(0.f, 0.f, 0.f, 0.f);
                if (col < N) v = *(const float4*)(Bf + (size_t)(kk + r) * ldb + col);
                rBf[i] = v;
            }
        } else if (BLAY == 1) {
            #pragma unroll
            for (int i = 0; i < WN / 2; i++) {
                int fidx = tid + i * 256;
                int r = fidx / (NCOLS / 8), c8 = fidx % (NCOLS / 8);
                int col = bn + c8 * 8;
                uint4 v = make_uint4(0, 0, 0, 0);
                if (col < N) v = *(const uint4*)(Bh + (size_t)(kk + r) * ldb + col);
                rBh[i] = v;
            }
        } else {
            #pragma unroll
            for (int i = 0; i < WN / 2; i++) {
                int fidx = tid + i * 256;
                int r = fidx >> 2, c8 = fidx & 3;
                uint4 v = make_uint4(0, 0, 0, 0);
                if (bn + r < N) v = *(const uint4*)(Bh + (size_t)(bn + r) * ldb + kk + c8 * 8);
                rBh[i] = v;
            }
        }
    };

    auto commit = [&](int buf) {
        #pragma unroll
        for (int i = 0; i < 2; i++) {
            int fidx = tid + i * 256;
            int r = fidx >> 2, c8 = fidx & 3;
            int slotblk = (c8 * 4) ^ swA(r);
            *(uint4*)&As32[buf][r * 16 + slotblk] = rA[i];
        }
        if (BLAY == 0) {
            uint16_t* Bs16 = (uint16_t*)Bs32[buf];
            #pragma unroll
            for (int i = 0; i < WN; i++) {
                int fidx = tid + i * 256;
                int r = fidx / (NCOLS / 4), c4 = fidx % (NCOLS / 4);
                int sig = r >> 1, odd = r & 1;
                float vv[4] = {rBf[i].x, rBf[i].y, rBf[i].z, rBf[i].w};
                #pragma unroll
                for (int j = 0; j < 4; j++) {
                    int col = c4 * 4 + j;
                    f16 hv = __float2half_rn(vv[j]);
                    Bs16[col * 32 + (sig ^ swB(col)) * 2 + odd] = *(uint16_t*)&hv;
                }
            }
        } else if (BLAY == 1) {
            uint16_t* Bs16 = (uint16_t*)Bs32[buf];
            #pragma unroll
            for (int i = 0; i < WN / 2; i++) {
                int fidx = tid + i * 256;
                int r = fidx / (NCOLS / 8), c8 = fidx % (NCOLS / 8);
                int sig = r >> 1, odd = r & 1;
                const uint16_t* src = (const uint16_t*)&rBh[i];
                #pragma unroll
                for (int j = 0; j < 8; j++) {
                    int col = c8 * 8 + j;
                    Bs16[col * 32 + (sig ^ swB(col)) * 2 + odd] = src[j];
                }
            }
        } else {
            #pragma unroll
            for (int i = 0; i < WN / 2; i++) {
                int fidx = tid + i * 256;
                int r = fidx >> 2, c8 = fidx & 3;
                int slotblk = (c8 * 4) ^ swA(r);
                *(uint4*)&Bs32[buf][r * 16 + slotblk] = rBh[i];
            }
        }
    };

    auto compute = [&](int buf) {
        #pragma unroll
        for (int ks = 0; ks < 2; ks++) {
            int sb = ks * 8;
            uint32_t afr[WN][4], bfr[4][2];
            #pragma unroll
            for (int mt = 0; mt < WN; mt++) {
                int r0 = m0w + mt * 16 + g;
                int r1 = r0 + 8;
                afr[mt][0] = As32[buf][r0 * 16 + ((sb + tg) ^ swA(r0))];
                afr[mt][1] = As32[buf][r1 * 16 + ((sb + tg) ^ swA(r1))];
                afr[mt][2] = As32[buf][r0 * 16 + ((sb + tg + 4) ^ swA(r0))];
                afr[mt][3] = As32[buf][r1 * 16 + ((sb + tg + 4) ^ swA(r1))];
            }
            #pragma unroll
            for (int nt = 0; nt < 4; nt++) {
                int c0 = n0w + nt * 8 + g;
                int sw = (BLAY == 2) ? swA(c0) : swB(c0);
                bfr[nt][0] = Bs32[buf][c0 * 16 + ((sb + tg) ^ sw)];
                bfr[nt][1] = Bs32[buf][c0 * 16 + ((sb + tg + 4) ^ sw)];
            }
            #pragma unroll
            for (int mt = 0; mt < WN; mt++)
                #pragma unroll
                for (int nt = 0; nt < 4; nt++)
                    mma_f16(cacc[mt][nt], afr[mt], bfr[nt]);
        }
    };

    stage(0);
    commit(0);
    if (Keff > 32) stage(32);
    __syncthreads();
    int buf = 0;
    for (int kk = 0; kk < Keff; kk += 32) {
        if (kk + 32 < Keff) {
            commit(buf ^ 1);
            if (kk + 64 < Keff) stage(kk + 64);
        }
        compute(buf);
        __syncthreads();
        buf ^= 1;
    }

    float* Cf = (float*)Cv + offC;
    f16* Ch = (f16*)Cv + offC;
    #pragma unroll
    for (int mt = 0; mt < WN; mt++) {
        #pragma unroll
        for (int half_ = 0; half_ < 2; half_++) {
            int lr = bm + m0w + mt * 16 + g + half_ * 8;
            bool rowok = (MODE == 0) ? (lr < M) : (lr < cnt);
            if (!rowok) continue;
            size_t orow = (MODE == 0) ? (size_t)lr : (size_t)(base + lr);
            float scale = (MODE == 2) ? g_perm_w[base + lr] : 1.f;
            #pragma unroll
            for (int nt = 0; nt < 4; nt++) {
                int col = bn + n0w + nt * 8 + 2 * tg;
                if (col >= N) continue;
                float v0 = cacc[mt][nt][half_ * 2 + 0];
                float v1 = cacc[mt][nt][half_ * 2 + 1];
                if (MODE == 2) { v0 *= scale; v1 *= scale; }
                if (CBF) {
                    *(__half2*)(Ch + orow * ldc + col) = __floats2half2_rn(v0, v1);
                } else {
                    if (MODE == 0 && resid) {
                        float2 rv = *(const float2*)(resid + orow * ldc + col);
                        v0 += rv.x; v1 += rv.y;
                    }
                    *(float2*)(Cf + orow * ldc + col) = make_float2(v0, v1);
                }
            }
        }
    }
}

// ---------------- fused gated up-proj: C = silu(A@B1) * (A@B3), f16 out ----
// MODE 0: dense rows; MODE 1: rows gathered via g_perm_token (expert z).
// CTA tile: 128 x (WN*32).
template<int MODE, int WN>
__global__ void __launch_bounds__(256)
gemm_dual(const f16* __restrict__ A, const float* __restrict__ B1g,
          const float* __restrict__ B3g, f16* __restrict__ C,
          int M, int N, int K, int lda, long long strB) {
    const int NCOLS = WN * 32;
    __shared__ uint32_t As32[2][2048];
    __shared__ uint32_t B1s32[2][WN * 512];
    __shared__ uint32_t B3s32[2][WN * 512];
    __shared__ int stoks[128];

    int tid = threadIdx.x;
    int warp = tid >> 5, lane = tid & 31;
    int g = lane >> 2, tg = lane & 3;
    int wm = warp / WN, wn = warp % WN;
    int m0w = wm * (WN * 16), n0w = wn * 32;

    int bn = blockIdx.x * NCOLS;
    int bm = blockIdx.y * 128;
    int z = blockIdx.z;

    int cnt = M, base = 0;
    if (MODE == 1) {
        cnt = g_counts[z];
        base = g_offsets[z];
        if (bm >= cnt) return;
        if (tid < 128) stoks[tid] = (bm + tid < cnt) ? g_perm_token[base + bm + tid] : 0;
        __syncthreads();
    }
    const float* B1 = B1g + (long long)z * strB;
    const float* B3 = B3g + (long long)z * strB;

    float acc1[WN][4][4], acc3[WN][4][4];
    #pragma unroll
    for (int a = 0; a < WN; a++)
        #pragma unroll
        for (int b = 0; b < 4; b++)
            #pragma unroll
            for (int c = 0; c < 4; c++) { acc1[a][b][c] = 0.f; acc3[a][b][c] = 0.f; }

    uint4 rA[2];
    float4 rB1[WN], rB3[WN];

    auto stage = [&](int kk) {
        #pragma unroll
        for (int i = 0; i < 2; i++) {
            int fidx = tid + i * 256;
            int r = fidx >> 2, c8 = fidx & 3;
            uint4 v = make_uint4(0, 0, 0, 0);
            if (MODE == 0) {
                if (bm + r < M) v = *(const uint4*)(A + (size_t)(bm + r) * lda + kk + c8 * 8);
            } else {
                if (bm + r < cnt) {
                    int tok = stoks[r];
                    v = *(const uint4*)(A + (size_t)tok * lda + kk + c8 * 8);
                }
            }
            rA[i] = v;
        }
        #pragma unroll
        for (int i = 0; i < WN; i++) {
            int fidx = tid + i * 256;
            int r = fidx / (NCOLS / 4), c4 = fidx % (NCOLS / 4);
            int col = bn + c4 * 4;
            float4 v1 = make_float4(0.f, 0.f, 0.f, 0.f);
            float4 v3 = v1;
            if (col < N) {
                v1 = *(const float4*)(B1 + (size_t)(kk + r) * N + col);
                v3 = *(const float4*)(B3 + (size_t)(kk + r) * N + col);
            }
            rB1[i] = v1; rB3[i] = v3;
        }
    };

    auto commit = [&](int buf) {
        #pragma unroll
        for (int i = 0; i < 2; i++) {
            int fidx = tid + i * 256;
            int r = fidx >> 2, c8 = fidx & 3;
            int slotblk = (c8 * 4) ^ swA(r);
            *(uint4*)&As32[buf][r * 16 + slotblk] = rA[i];
        }
        uint16_t* b1 = (uint16_t*)B1s32[buf];
        uint16_t* b3 = (uint16_t*)B3s32[buf];
        #pragma unroll
        for (int i = 0; i < WN; i++) {
            int fidx = tid + i * 256;
            int r = fidx / (NCOLS / 4), c4 = fidx % (NCOLS / 4);
            int sig = r >> 1, odd = r & 1;
            float w1[4] = {rB1[i].x, rB1[i].y, rB1[i].z, rB1[i].w};
            float w3[4] = {rB3[i].x, rB3[i].y, rB3[i].z, rB3[i].w};
            #pragma unroll
            for (int j = 0; j < 4; j++) {
                int col = c4 * 4 + j;
                int slot = (sig ^ swB(col)) * 2 + odd;
                f16 h1 = __float2half_rn(w1[j]);
                f16 h3 = __float2half_rn(w3[j]);
                b1[col * 32 + slot] = *(uint16_t*)&h1;
                b3[col * 32 + slot] = *(uint16_t*)&h3;
            }
        }
    };

    auto compute = [&](int buf) {
        #pragma unroll
        for (int ks = 0; ks < 2; ks++) {
            int sb = ks * 8;
            uint32_t afr[WN][4], b1fr[4][2], b3fr[4][2];
            #pragma unroll
            for (int mt = 0; mt < WN; mt++) {
                int r0 = m0w + mt * 16 + g;
                int r1 = r0 + 8;
                afr[mt][0] = As32[buf][r0 * 16 + ((sb + tg) ^ swA(r0))];
                afr[mt][1] = As32[buf][r1 * 16 + ((sb + tg) ^ swA(r1))];
                afr[mt][2] = As32[buf][r0 * 16 + ((sb + tg + 4) ^ swA(r0))];
                afr[mt][3] = As32[buf][r1 * 16 + ((sb + tg + 4) ^ swA(r1))];
            }
            #pragma unroll
            for (int nt = 0; nt < 4; nt++) {
                int c0 = n0w + nt * 8 + g;
                int sw = swB(c0);
                b1fr[nt][0] = B1s32[buf][c0 * 16 + ((sb + tg) ^ sw)];
                b1fr[nt][1] = B1s32[buf][c0 * 16 + ((sb + tg + 4) ^ sw)];
                b3fr[nt][0] = B3s32[buf][c0 * 16 + ((sb + tg) ^ sw)];
                b3fr[nt][1] = B3s32[buf][c0 * 16 + ((sb + tg + 4) ^ sw)];
            }
            #pragma unroll
            for (int mt = 0; mt < WN; mt++)
                #pragma unroll
                for (int nt = 0; nt < 4; nt++) {
                    mma_f16(acc1[mt][nt], afr[mt], b1fr[nt]);
                    mma_f16(acc3[mt][nt], afr[mt], b3fr[nt]);
                }
        }
    };

    stage(0);
    commit(0);
    if (K > 32) stage(32);
    __syncthreads();
    int buf = 0;
    for (int kk = 0; kk < K; kk += 32) {
        if (kk + 32 < K) {
            commit(buf ^ 1);
            if (kk + 64 < K) stage(kk + 64);
        }
        compute(buf);
        __syncthreads();
        buf ^= 1;
    }

    #pragma unroll
    for (int mt = 0; mt < WN; mt++) {
        #pragma unroll
        for (int half_ = 0; half_ < 2; half_++) {
            int lr = bm + m0w + mt * 16 + g + half_ * 8;
            bool rowok = (MODE == 0) ? (lr < M) : (lr < cnt);
            if (!rowok) continue;
            size_t orow = (MODE == 0) ? (size_t)lr : (size_t)(base + lr);
            #pragma unroll
            for (int nt = 0; nt < 4; nt++) {
                int col = bn + n0w + nt * 8 + 2 * tg;
                if (col >= N) continue;
                float a0 = acc1[mt][nt][half_ * 2 + 0];
                float a1 = acc1[mt][nt][half_ * 2 + 1];
                float b0 = acc3[mt][nt][half_ * 2 + 0];
                float b1 = acc3[mt][nt][half_ * 2 + 1];
                *(__half2*)(C + orow * N + col) =
                    __floats2half2_rn(silu_f(a0) * b0, silu_f(a1) * b1);
            }
        }
    }
}

// ---------------- pack per-head K ----------------
__global__ void prep_k_kernel(const f16* __restrict__ kvph, const float* __restrict__ kvF,
                              f16* __restrict__ kh) {
    long long i = (long long)blockIdx.x * 256 + threadIdx.x;
    if (i >= (long long)BH * SEQ * QK_HD) return;
    int d = (int)(i & 127);
    long long zs = i >> 7;
    int s = (int)(zs & (SEQ - 1));
    int zz = (int)(zs >> 10);
    int h = zz & 7, b = zz >> 3;
    size_t t = (size_t)b * SEQ + s;
    f16 val;
    if (d < NOPE) val = kvph[t * KVB_N + h * (NOPE + V_HD) + d];
    else          val = __float2half_rn(kvF[t * KVA_N + KV_LORA + (d - NOPE)]);
    kh[i] = val;
}

// ---------------- causal softmax ----------------
__global__ void softmax_kernel(const float* __restrict__ P, f16* __restrict__ Ph) {
    int r = blockIdx.x;
    long long zoff = (long long)blockIdx.y * SEQ * SEQ + (long long)r * SEQ;
    const float* row = P + zoff;
    f16* orow = Ph + zoff;
    int n = r + 1;
    int tid = threadIdx.x;
    float v[4];
    float m = -1e30f;
    #pragma unroll
    for (int j = 0; j < 4; j++) {
        int c = tid + j * 256;
        v[j] = (c < n) ? row[c] : -1e30f;
        m = fmaxf(m, v[j]);
    }
    m = blockReduceMax256(m);
    float e[4], l = 0.f;
    #pragma unroll
    for (int j = 0; j < 4; j++) {
        int c = tid + j * 256;
        e[j] = (c < n) ? __expf(ATTN_SCALE * (v[j] - m)) : 0.f;
        l += e[j];
    }
    l = blockReduceSum256(l);
    float inv = 1.f / l;
    #pragma unroll
    for (int j = 0; j < 4; j++) {
        int c = tid + j * 256;
        orow[c] = __float2half_rn(e[j] * inv);
    }
}

// ---------------- gate / routing ----------------
__global__ void zero_counts_kernel() {
    if (threadIdx.x < N_EXP) g_counts[threadIdx.x] = 0;
}

__global__ void gate_kernel(const float* __restrict__ xf, const float* __restrict__ gw,
                            const float* __restrict__ gb) {
    int t = blockIdx.x;
    __shared__ float sscore[N_EXP];
    int tid = threadIdx.x, warp = tid >> 5, lane = tid & 31;
    for (int e = warp; e < N_EXP; e += 4) {
        float s = 0.f;
        for (int d = lane; d < DIM; d += 32) s += xf[(size_t)t * DIM + d] * gw[(size_t)e * DIM + d];
        #pragma unroll
        for (int o = 16; o > 0; o >>= 1) s += __shfl_xor_sync(0xffffffffu, s, o);
        if (lane == 0) sscore[e] = 1.f / (1.f + expf(-s));
    }
    __syncthreads();
    if (tid == 0) {
        float orig[N_EXP], s[N_EXP];
        for (int e = 0; e < N_EXP; e++) { orig[e] = sscore[e]; s[e] = orig[e] + gb[e]; }
        float gs[N_GROUPS];
        for (int gg = 0; gg < N_GROUPS; gg++) {
            float m1 = -1e30f, m2 = -1e30f;
            for (int k = 0; k < 4; k++) {
                float v = s[gg * 4 + k];
                if (v > m1) { m2 = m1; m1 = v; } else if (v > m2) m2 = v;
            }
            gs[gg] = m1 + m2;
        }
        bool gsel[N_GROUPS] = {};
        for (int r = 0; r < TOPK_G; r++) {
            int best = -1; float bv = -1e30f;
            for (int gg = 0; gg < N_GROUPS; gg++)
                if (!gsel[gg] && gs[gg] > bv) { bv = gs[gg]; best = gg; }
            gsel[best] = true;
        }
        for (int gg = 0; gg < N_GROUPS; gg++)
            if (!gsel[gg]) for (int k = 0; k < 4; k++) s[gg * 4 + k] = -1e30f;
        int idx[TOPK]; bool used[N_EXP] = {};
        for (int r = 0; r < TOPK; r++) {
            int best = -1; float bv = -2e30f;
            for (int e = 0; e < N_EXP; e++)
                if (!used[e] && s[e] > bv) { bv = s[e]; best = e; }
            used[best] = true; idx[r] = best;
        }
        float wsum = 0.f;
        for (int r = 0; r < TOPK; r++) wsum += orig[idx[r]];
        float inv = 1.f / (wsum + 1e-20f);
        for (int r = 0; r < TOPK; r++) {
            g_expt_idx[t * TOPK + r] = idx[r];
            g_expt_w[t * TOPK + r] = orig[idx[r]] * inv;
            atomicAdd(&g_counts[idx[r]], 1);
        }
    }
}

__global__ void offsets_kernel() {
    if (threadIdx.x == 0) {
        int acc = 0;
        for (int e = 0; e < N_EXP; e++) {
            g_offsets[e] = acc;
            g_cursor[e] = acc;
            acc += g_counts[e];
        }
    }
}

__global__ void scatter_kernel() {
    int i = blockIdx.x * blockDim.x + threadIdx.x;
    if (i < NSLOT) {
        int e = g_expt_idx[i];
        int pos = atomicAdd(&g_cursor[e], 1);
        g_perm_token[pos] = i >> 2;
        g_perm_w[pos] = g_expt_w[i];
        g_slot_of[i] = pos;
    }
}

// ---------------- final combine (float4) ----------------
__global__ void final_kernel(float* __restrict__ out) {
    int t = blockIdx.x;
    int s0 = g_slot_of[t * 4 + 0], s1 = g_slot_of[t * 4 + 1];
    int s2 = g_slot_of[t * 4 + 2], s3 = g_slot_of[t * 4 + 3];
    int i = threadIdx.x;
    const float4* x2v = (const float4*)(g_x2 + (size_t)t * DIM);
    const float4* zbv = (const float4*)(g_zb + (size_t)t * DIM);
    const float4* y0 = (const float4*)(g_ybuf + (size_t)s0 * DIM);
    const float4* y1 = (const float4*)(g_ybuf + (size_t)s1 * DIM);
    const float4* y2 = (const float4*)(g_ybuf + (size_t)s2 * DIM);
    const float4* y3 = (const float4*)(g_ybuf + (size_t)s3 * DIM);
    float4 a = x2v[i], b = zbv[i], c0 = y0[i], c1 = y1[i], c2 = y2[i], c3 = y3[i];
    float4 r = make_float4(a.x + b.x + c0.x + c1.x + c2.x + c3.x,
                           a.y + b.y + c0.y + c1.y + c2.y + c3.y,
                           a.z + b.z + c0.z + c1.z + c2.z + c3.z,
                           a.w + b.w + c0.w + c1.w + c2.w + c3.w);
    *(float4*)(out + (size_t)t * DIM + i * 4) = r;
}

// ---------------- launcher ----------------
extern "C" void kernel_launch(void* const* d_in, const int* in_sizes, int n_in,
                              void* d_out, int out_size) {
    const float* x       = (const float*)d_in[0];
    const float* norm_a  = (const float*)d_in[1];
    const float* wq      = (const float*)d_in[2];
    const float* wkv_a   = (const float*)d_in[3];
    const float* kvnw    = (const float*)d_in[4];
    const float* wkv_b   = (const float*)d_in[5];
    const float* wo      = (const float*)d_in[6];
    const float* norm_m  = (const float*)d_in[7];
    const float* gate_w  = (const float*)d_in[8];
    const float* gate_b  = (const float*)d_in[9];
    const float* ew1     = (const float*)d_in[10];
    const float* ew2     = (const float*)d_in[11];
    const float* ew3     = (const float*)d_in[12];
    const float* sw1     = (const float*)d_in[13];
    const float* sw2     = (const float*)d_in[14];
    const float* sw3     = (const float*)d_in[15];
    float* out = (float*)d_out;

    float *kvF, *x2, *xf, *ybuf, *zb, *P;
    f16 *x1h, *qh, *cnh, *kvph, *khh, *Ph, *attnh, *xfh, *hbufh, *hsh;
    cudaGetSymbolAddress((void**)&kvF, g_kvF);
    cudaGetSymbolAddress((void**)&x2,  g_x2);
    cudaGetSymbolAddress((void**)&xf,  g_xf);
    cudaGetSymbolAddress((void**)&ybuf,g_ybuf);
    cudaGetSymbolAddress((void**)&zb,  g_zb);
    cudaGetSymbolAddress((void**)&P,   g_P);
    cudaGetSymbolAddress((void**)&x1h, g_x1h);
    cudaGetSymbolAddress((void**)&qh,  g_qh);
    cudaGetSymbolAddress((void**)&cnh, g_cnh);
    cudaGetSymbolAddress((void**)&kvph,g_kvph);
    cudaGetSymbolAddress((void**)&khh, g_khh);
    cudaGetSymbolAddress((void**)&Ph,  g_Ph);
    cudaGetSymbolAddress((void**)&attnh, g_attnh);
    cudaGetSymbolAddress((void**)&xfh, g_xfh);
    cudaGetSymbolAddress((void**)&hbufh, g_hbufh);
    cudaGetSymbolAddress((void**)&hsh, g_hsh);

    // 1) attention input norm -> fp16
    rmsnorm_kernel<<<TTOK, 256>>>(x, norm_a, nullptr, x1h, DIM, DIM);
    // 2) q = x1 @ wq (128x64 tiles -> 256 CTAs)
    gemm_k<0,0,true,0,2><<<dim3(16,16,1), 256>>>(x1h, wq, qh, nullptr,
        TTOK, DIM, DIM, DIM, DIM, DIM, 1, 0,0,0,0,0,0);
    // 3) kv = x1 @ wkv_a (N=320 -> 5 n-tiles of 64)
    gemm_k<0,0,false,0,2><<<dim3(5,16,1), 256>>>(x1h, wkv_a, kvF, nullptr,
        TTOK, KVA_N, DIM, DIM, KVA_N, KVA_N, 1, 0,0,0,0,0,0);
    // 4) cn = rmsnorm(kv[:, :256])
    rmsnorm_kernel<<<TTOK, 256>>>(kvF, kvnw, nullptr, cnh, KV_LORA, KVA_N);
    // 5) kvp = cn @ wkv_b
    gemm_k<0,0,true,0,2><<<dim3(24,16,1), 256>>>(cnh, wkv_b, kvph, nullptr,
        TTOK, KVB_N, KV_LORA, KV_LORA, KVB_N, KVB_N, 1, 0,0,0,0,0,0);
    // 6) pack per-head K
    prep_k_kernel<<<(int)(((long long)BH*SEQ*QK_HD + 255)/256), 256>>>(kvph, kvF, khh);
    // 7) scores = q @ kh^T, lower-triangular 128x128 tiles (proven WN=4)
    gemm_k<0,2,false,1,4><<<dim3(36,1,BH), 256>>>(qh, khh, P, nullptr,
        SEQ, SEQ, QK_HD, DIM, QK_HD, SEQ, HEADS,
        (long long)SEQ*DIM, 128,
        (long long)HEADS*SEQ*QK_HD, (long long)SEQ*QK_HD,
        (long long)HEADS*SEQ*SEQ, (long long)SEQ*SEQ);
    // 8) causal softmax -> normalized fp16 P
    softmax_kernel<<<dim3(SEQ, BH), 256>>>(P, Ph);
    // 9) attn = P @ V, N-split 128x64 tiles (256 CTAs), causal K-limit
    gemm_k<0,1,true,2,2><<<dim3(2,8,BH), 256>>>(Ph, kvph + NOPE, attnh, nullptr,
        SEQ, V_HD, SEQ, SEQ, KVB_N, DIM, HEADS,
        (long long)HEADS*SEQ*SEQ, (long long)SEQ*SEQ,
        (long long)SEQ*KVB_N, (long long)(NOPE+V_HD),
        (long long)SEQ*DIM, 128);
    // 10) x2 = x + attn @ wo
    gemm_k<0,0,false,0,2><<<dim3(16,16,1), 256>>>(attnh, wo, x2, x,
        TTOK, DIM, DIM, DIM, DIM, DIM, 1, 0,0,0,0,0,0);
    // 11) moe input norm
    rmsnorm_kernel<<<TTOK, 256>>>(x2, norm_m, xf, xfh, DIM, DIM);
    // 12) gate + routing
    zero_counts_kernel<<<1, 32>>>();
    gate_kernel<<<TTOK, 128>>>(xf, gate_w, gate_b);
    offsets_kernel<<<1, 32>>>();
    scatter_kernel<<<NSLOT/256, 256>>>();
    // 13) routed experts: fused gated up-proj (WN=2), weighted down-proj (proven WN=4)
    gemm_dual<1,2><<<dim3(8,16,N_EXP), 256>>>(xfh, ew1, ew3, hbufh,
        0, INTER, DIM, DIM, (long long)DIM*INTER);
    gemm_k<2,0,false,0,4><<<dim3(8,16,N_EXP), 256>>>(hbufh, ew2, ybuf, nullptr,
        0, DIM, INTER, INTER, DIM, DIM, 1, 0,0, (long long)INTER*DIM,0, 0,0);
    // 14) shared expert: fused gated up-proj (WN=2), down-proj (WN=2)
    gemm_dual<0,2><<<dim3(8,16,1), 256>>>(xfh, sw1, sw3, hsh,
        TTOK, INTER, DIM, DIM, 0);
    gemm_k<0,0,false,0,2><<<dim3(16,16,1), 256>>>(hsh, sw2, zb, nullptr,
        TTOK, DIM, INTER, INTER, DIM, DIM, 1, 0,0,0,0,0,0);
    // 15) final combine
    final_kernel<<<TTOK, 256>>>(out);
}

// round 10
// speedup vs baseline: 1.6612x; 1.0443x over previous
#include <cuda_runtime.h>
#include <cuda_fp16.h>
#include <math.h>
#include <stdint.h>

// ---------------- problem constants ----------------
#define TTOK   2048
#define BATCH  2
#define SEQ    1024
#define DIM    1024
#define HEADS  8
#define BH     16
#define QK_HD  128
#define V_HD   128
#define NOPE   64
#define ROPE   64
#define KV_LORA 256
#define KVA_N  320
#define KVB_N  1536
#define N_EXP  32
#define N_GROUPS 8
#define TOPK   4
#define TOPK_G 4
#define INTER  512
#define NSLOT  8192
#define EPS    1e-6f
#define ATTN_SCALE 0.08838834764831843f

typedef __half f16;

// ---------------- scratch ----------------
__device__ float g_kvF [TTOK * KVA_N];
__device__ float g_x2  [TTOK * DIM];
__device__ float g_xf  [TTOK * DIM];
__device__ float g_ybuf[NSLOT * DIM];
__device__ float g_zb  [TTOK * DIM];
__device__ float g_P   [(size_t)BH * SEQ * SEQ];

__device__ f16 g_x1h [TTOK * DIM];
__device__ f16 g_qh  [TTOK * DIM];
__device__ f16 g_cnh [TTOK * KV_LORA];
__device__ f16 g_kvph[TTOK * KVB_N];
__device__ f16 g_khh [(size_t)BH * SEQ * QK_HD];
__device__ f16 g_Ph  [(size_t)BH * SEQ * SEQ];
__device__ f16 g_attnh[TTOK * DIM];
__device__ f16 g_xfh [TTOK * DIM];
__device__ f16 g_hbufh[NSLOT * INTER];
__device__ f16 g_hsh [TTOK * INTER];

__device__ int   g_counts [N_EXP];
__device__ int   g_offsets[N_EXP];
__device__ int   g_cursor [N_EXP];
__device__ int   g_expt_idx[NSLOT];
__device__ float g_expt_w [NSLOT];
__device__ int   g_perm_token[NSLOT];
__device__ float g_perm_w   [NSLOT];
__device__ int   g_slot_of  [NSLOT];

// ---------------- helpers ----------------
__device__ __forceinline__ float blockReduceSum256(float v) {
    __shared__ float red[8];
    int lane = threadIdx.x & 31, warp = threadIdx.x >> 5;
    #pragma unroll
    for (int o = 16; o > 0; o >>= 1) v += __shfl_xor_sync(0xffffffffu, v, o);
    if (lane == 0) red[warp] = v;
    __syncthreads();
    if (warp == 0) {
        v = (lane < 8) ? red[lane] : 0.f;
        #pragma unroll
        for (int o = 4; o > 0; o >>= 1) v += __shfl_xor_sync(0xffffffffu, v, o);
        if (lane == 0) red[0] = v;
    }
    __syncthreads();
    return red[0];
}

__device__ __forceinline__ float blockReduceMax256(float v) {
    __shared__ float red[8];
    int lane = threadIdx.x & 31, warp = threadIdx.x >> 5;
    #pragma unroll
    for (int o = 16; o > 0; o >>= 1) v = fmaxf(v, __shfl_xor_sync(0xffffffffu, v, o));
    if (lane == 0) red[warp] = v;
    __syncthreads();
    if (warp == 0) {
        v = (lane < 8) ? red[lane] : -1e30f;
        #pragma unroll
        for (int o = 4; o > 0; o >>= 1) v = fmaxf(v, __shfl_xor_sync(0xffffffffu, v, o));
        if (lane == 0) red[0] = v;
    }
    __syncthreads();
    return red[0];
}

__device__ __forceinline__ void mma_f16(float* c, const uint32_t* a, const uint32_t* b) {
    asm volatile(
        "mma.sync.aligned.m16n8k16.row.col.f32.f16.f16.f32 "
        "{%0,%1,%2,%3}, {%4,%5,%6,%7}, {%8,%9}, {%0,%1,%2,%3};\n"
        : "+f"(c[0]), "+f"(c[1]), "+f"(c[2]), "+f"(c[3])
        : "r"(a[0]), "r"(a[1]), "r"(a[2]), "r"(a[3]), "r"(b[0]), "r"(b[1]));
}

__device__ __forceinline__ int swA(int row) { return ((row >> 1) & 3) << 2; }
__device__ __forceinline__ int swB(int col) { return (((col >> 1) & 3) << 2) ^ ((col >> 2) & 3); }

__device__ __forceinline__ float silu_f(float a) { return a / (1.f + __expf(-a)); }

// ---------------- rmsnorm (float4 vectorized) ----------------
__global__ void rmsnorm_kernel(const float* __restrict__ x, const float* __restrict__ w,
                               float* __restrict__ o32, f16* __restrict__ o16,
                               int D, int in_stride) {
    int t = blockIdx.x;
    const float4* row = (const float4*)(x + (size_t)t * in_stride);
    const float4* wv4 = (const float4*)w;
    int nv = D >> 2;
    float ss = 0.f;
    for (int i = threadIdx.x; i < nv; i += 256) {
        float4 v = row[i];
        ss += v.x * v.x + v.y * v.y + v.z * v.z + v.w * v.w;
    }
    ss = blockReduceSum256(ss);
    __shared__ float inv;
    if (threadIdx.x == 0) inv = rsqrtf(ss / (float)D + EPS);
    __syncthreads();
    float iv = inv;
    for (int i = threadIdx.x; i < nv; i += 256) {
        float4 v = row[i];
        float4 wv = wv4[i];
        float4 r = make_float4(v.x * iv * wv.x, v.y * iv * wv.y,
                               v.z * iv * wv.z, v.w * iv * wv.w);
        if (o32) *(float4*)(o32 + (size_t)t * D + i * 4) = r;
        if (o16) {
            __half2* oh = (__half2*)(o16 + (size_t)t * D + i * 4);
            oh[0] = __floats2half2_rn(r.x, r.y);
            oh[1] = __floats2half2_rn(r.z, r.w);
        }
    }
}

// ---------------- fp16 tensor-core GEMM -----------------------------------
// CTA tile: 128 x (WN*32). 8 warps as (8/WN) x WN; per-warp WN m-subtiles x 4 n-subtiles.
// MODE 0: dense; MODE 1: A rows gathered via g_perm_token (expert z);
// MODE 2: A rows at expert offset, C scaled by g_perm_w.
// BLAY: 0 = B fp32 [K][N]; 1 = B f16 [K][N]; 2 = B f16 [N][K].
// CBF: C f16 (else fp32 + optional resid in MODE 0).
// CAUSAL: 0 none; 1 = triangular tile decode (bn tiles of NCOLS under bm+128);
//         2 = K clipped at bm+128.
template<int MODE, int BLAY, bool CBF, int CAUSAL, int WN>
__global__ void __launch_bounds__(256)
gemm_k(const f16* __restrict__ A, const void* __restrict__ Bv, void* __restrict__ Cv,
       const float* __restrict__ resid,
       int M, int N, int K, int lda, int ldb, int ldc, int zdiv,
       long long sA1, long long sA2, long long sB1, long long sB2,
       long long sC1, long long sC2) {
    const int NCOLS = WN * 32;
    __shared__ uint32_t As32[2][2048];
    __shared__ uint32_t Bs32[2][WN * 512];
    __shared__ int stoks[128];

    int tid = threadIdx.x;
    int warp = tid >> 5, lane = tid & 31;
    int g = lane >> 2, tg = lane & 3;
    int wm = warp / WN, wn = warp % WN;
    int m0w = wm * (WN * 16), n0w = wn * 32;

    int bn, bm;
    if (CAUSAL == 1) {
        // triangular tiles: bm rows of 128, bn tiles of NCOLS with bn <= bm+127.
        // tiles per bm-row-block = R*(bmt+1), R = 128/NCOLS; cumulative R*m(m+1)/2.
        const int R = 128 / NCOLS;
        int ti = blockIdx.x;
        int bmt = 0;
        while (R * (bmt + 1) * (bmt + 2) / 2 <= ti) bmt++;
        int bnt = ti - R * bmt * (bmt + 1) / 2;
        bm = bmt * 128; bn = bnt * NCOLS;
    } else {
        bn = blockIdx.x * NCOLS;
        bm = blockIdx.y * 128;
    }
    int z = blockIdx.z;
    long long offA = (long long)(z / zdiv) * sA1 + (long long)(z % zdiv) * sA2;
    long long offB = (long long)(z / zdiv) * sB1 + (long long)(z % zdiv) * sB2;
    long long offC = (long long)(z / zdiv) * sC1 + (long long)(z % zdiv) * sC2;

    int cnt = M, base = 0;
    if (MODE != 0) {
        cnt = g_counts[z];
        base = g_offsets[z];
        if (bm >= cnt) return;
    }
    if (MODE == 1) {
        if (tid < 128) stoks[tid] = (bm + tid < cnt) ? g_perm_token[base + bm + tid] : 0;
        __syncthreads();
    }

    const f16* Ap = A + offA;
    const float* Bf = (BLAY == 0) ? ((const float*)Bv + offB) : nullptr;
    const f16*  Bh = (BLAY != 0) ? ((const f16*)Bv + offB) : nullptr;

    int Keff = K;
    if (CAUSAL == 2) { int kl = bm + 128; Keff = kl < K ? kl : K; }

    float cacc[WN][4][4];
    #pragma unroll
    for (int a = 0; a < WN; a++)
        #pragma unroll
        for (int b = 0; b < 4; b++)
            #pragma unroll
            for (int c = 0; c < 4; c++) cacc[a][b][c] = 0.f;

    uint4 rA[2];
    float4 rBf[WN];
    uint4 rBh[WN / 2];

    auto stage = [&](int kk) {
        #pragma unroll
        for (int i = 0; i < 2; i++) {
            int fidx = tid + i * 256;
            int r = fidx >> 2, c8 = fidx & 3;
            uint4 v = make_uint4(0, 0, 0, 0);
            if (MODE == 0) {
                int row = bm + r;
                if (row < M) v = *(const uint4*)(Ap + (size_t)row * lda + kk + c8 * 8);
            } else if (MODE == 1) {
                if (bm + r < cnt) {
                    int tok = stoks[r];
                    v = *(const uint4*)(Ap + (size_t)tok * lda + kk + c8 * 8);
                }
            } else {
                if (bm + r < cnt)
                    v = *(const uint4*)(Ap + (size_t)(base + bm + r) * lda + kk + c8 * 8);
            }
            rA[i] = v;
        }
        if (BLAY == 0) {
            #pragma unroll
            for (int i = 0; i < WN; i++) {
                int fidx = tid + i * 256;
                int r = fidx / (NCOLS / 4), c4 = fidx % (NCOLS / 4);
                int col = bn + c4 * 4;
                float4 v = make_float4(0.f, 0.f, 0.f, 0.f);
                if (col < N) v = *(const float4*)(Bf + (size_t)(kk + r) * ldb + col);
                rBf[i] = v;
            }
        } else if (BLAY == 1) {
            #pragma unroll
            for (int i = 0; i < WN / 2; i++) {
                int fidx = tid + i * 256;
                int r = fidx / (NCOLS / 8), c8 = fidx % (NCOLS / 8);
                int col = bn + c8 * 8;
                uint4 v = make_uint4(0, 0, 0, 0);
                if (col < N) v = *(const uint4*)(Bh + (size_t)(kk + r) * ldb + col);
                rBh[i] = v;
            }
        } else {
            #pragma unroll
            for (int i = 0; i < WN / 2; i++) {
                int fidx = tid + i * 256;
                int r = fidx >> 2, c8 = fidx & 3;
                uint4 v = make_uint4(0, 0, 0, 0);
                if (bn + r < N) v = *(const uint4*)(Bh + (size_t)(bn + r) * ldb + kk + c8 * 8);
                rBh[i] = v;
            }
        }
    };

    auto commit = [&](int buf) {
        #pragma unroll
        for (int i = 0; i < 2; i++) {
            int fidx = tid + i * 256;
            int r = fidx >> 2, c8 = fidx & 3;
            int slotblk = (c8 * 4) ^ swA(r);
            *(uint4*)&As32[buf][r * 16 + slotblk] = rA[i];
        }
        if (BLAY == 0) {
            uint16_t* Bs16 = (uint16_t*)Bs32[buf];
            #pragma unroll
            for (int i = 0; i < WN; i++) {
                int fidx = tid + i * 256;
                int r = fidx / (NCOLS / 4), c4 = fidx % (NCOLS / 4);
                int sig = r >> 1, odd = r & 1;
                float vv[4] = {rBf[i].x, rBf[i].y, rBf[i].z, rBf[i].w};
                #pragma unroll
                for (int j = 0; j < 4; j++) {
                    int col = c4 * 4 + j;
                    f16 hv = __float2half_rn(vv[j]);
                    Bs16[col * 32 + (sig ^ swB(col)) * 2 + odd] = *(uint16_t*)&hv;
                }
            }
        } else if (BLAY == 1) {
            uint16_t* Bs16 = (uint16_t*)Bs32[buf];
            #pragma unroll
            for (int i = 0; i < WN / 2; i++) {
                int fidx = tid + i * 256;
                int r = fidx / (NCOLS / 8), c8 = fidx % (NCOLS / 8);
                int sig = r >> 1, odd = r & 1;
                const uint16_t* src = (const uint16_t*)&rBh[i];
                #pragma unroll
                for (int j = 0; j < 8; j++) {
                    int col = c8 * 8 + j;
                    Bs16[col * 32 + (sig ^ swB(col)) * 2 + odd] = src[j];
                }
            }
        } else {
            #pragma unroll
            for (int i = 0; i < WN / 2; i++) {
                int fidx = tid + i * 256;
                int r = fidx >> 2, c8 = fidx & 3;
                int slotblk = (c8 * 4) ^ swA(r);
                *(uint4*)&Bs32[buf][r * 16 + slotblk] = rBh[i];
            }
        }
    };

    auto compute = [&](int buf) {
        #pragma unroll
        for (int ks = 0; ks < 2; ks++) {
            int sb = ks * 8;
            uint32_t afr[WN][4], bfr[4][2];
            #pragma unroll
            for (int mt = 0; mt < WN; mt++) {
                int r0 = m0w + mt * 16 + g;
                int r1 = r0 + 8;
                afr[mt][0] = As32[buf][r0 * 16 + ((sb + tg) ^ swA(r0))];
                afr[mt][1] = As32[buf][r1 * 16 + ((sb + tg) ^ swA(r1))];
                afr[mt][2] = As32[buf][r0 * 16 + ((sb + tg + 4) ^ swA(r0))];
                afr[mt][3] = As32[buf][r1 * 16 + ((sb + tg + 4) ^ swA(r1))];
            }
            #pragma unroll
            for (int nt = 0; nt < 4; nt++) {
                int c0 = n0w + nt * 8 + g;
                int sw = (BLAY == 2) ? swA(c0) : swB(c0);
                bfr[nt][0] = Bs32[buf][c0 * 16 + ((sb + tg) ^ sw)];
                bfr[nt][1] = Bs32[buf][c0 * 16 + ((sb + tg + 4) ^ sw)];
            }
            #pragma unroll
            for (int mt = 0; mt < WN; mt++)
                #pragma unroll
                for (int nt = 0; nt < 4; nt++)
                    mma_f16(cacc[mt][nt], afr[mt], bfr[nt]);
        }
    };

    stage(0);
    commit(0);
    if (Keff > 32) stage(32);
    __syncthreads();
    int buf = 0;
    for (int kk = 0; kk < Keff; kk += 32) {
        if (kk + 32 < Keff) {
            commit(buf ^ 1);
            if (kk + 64 < Keff) stage(kk + 64);
        }
        compute(buf);
        __syncthreads();
        buf ^= 1;
    }

    float* Cf = (float*)Cv + offC;
    f16* Ch = (f16*)Cv + offC;
    #pragma unroll
    for (int mt = 0; mt < WN; mt++) {
        #pragma unroll
        for (int half_ = 0; half_ < 2; half_++) {
            int lr = bm + m0w + mt * 16 + g + half_ * 8;
            bool rowok = (MODE == 0) ? (lr < M) : (lr < cnt);
            if (!rowok) continue;
            size_t orow = (MODE == 0) ? (size_t)lr : (size_t)(base + lr);
            float scale = (MODE == 2) ? g_perm_w[base + lr] : 1.f;
            #pragma unroll
            for (int nt = 0; nt < 4; nt++) {
                int col = bn + n0w + nt * 8 + 2 * tg;
                if (col >= N) continue;
                float v0 = cacc[mt][nt][half_ * 2 + 0];
                float v1 = cacc[mt][nt][half_ * 2 + 1];
                if (MODE == 2) { v0 *= scale; v1 *= scale; }
                if (CBF) {
                    *(__half2*)(Ch + orow * ldc + col) = __floats2half2_rn(v0, v1);
                } else {
                    if (MODE == 0 && resid) {
                        float2 rv = *(const float2*)(resid + orow * ldc + col);
                        v0 += rv.x; v1 += rv.y;
                    }
                    *(float2*)(Cf + orow * ldc + col) = make_float2(v0, v1);
                }
            }
        }
    }
}

// ---------------- fused gated up-proj: C = silu(A@B1) * (A@B3), f16 out ----
// MODE 0: dense rows; MODE 1: rows gathered via g_perm_token (expert z).
// CTA tile: 128 x (WN*32).
template<int MODE, int WN>
__global__ void __launch_bounds__(256)
gemm_dual(const f16* __restrict__ A, const float* __restrict__ B1g,
          const float* __restrict__ B3g, f16* __restrict__ C,
          int M, int N, int K, int lda, long long strB) {
    const int NCOLS = WN * 32;
    __shared__ uint32_t As32[2][2048];
    __shared__ uint32_t B1s32[2][WN * 512];
    __shared__ uint32_t B3s32[2][WN * 512];
    __shared__ int stoks[128];

    int tid = threadIdx.x;
    int warp = tid >> 5, lane = tid & 31;
    int g = lane >> 2, tg = lane & 3;
    int wm = warp / WN, wn = warp % WN;
    int m0w = wm * (WN * 16), n0w = wn * 32;

    int bn = blockIdx.x * NCOLS;
    int bm = blockIdx.y * 128;
    int z = blockIdx.z;

    int cnt = M, base = 0;
    if (MODE == 1) {
        cnt = g_counts[z];
        base = g_offsets[z];
        if (bm >= cnt) return;
        if (tid < 128) stoks[tid] = (bm + tid < cnt) ? g_perm_token[base + bm + tid] : 0;
        __syncthreads();
    }
    const float* B1 = B1g + (long long)z * strB;
    const float* B3 = B3g + (long long)z * strB;

    float acc1[WN][4][4], acc3[WN][4][4];
    #pragma unroll
    for (int a = 0; a < WN; a++)
        #pragma unroll
        for (int b = 0; b < 4; b++)
            #pragma unroll
            for (int c = 0; c < 4; c++) { acc1[a][b][c] = 0.f; acc3[a][b][c] = 0.f; }

    uint4 rA[2];
    float4 rB1[WN], rB3[WN];

    auto stage = [&](int kk) {
        #pragma unroll
        for (int i = 0; i < 2; i++) {
            int fidx = tid + i * 256;
            int r = fidx >> 2, c8 = fidx & 3;
            uint4 v = make_uint4(0, 0, 0, 0);
            if (MODE == 0) {
                if (bm + r < M) v = *(const uint4*)(A + (size_t)(bm + r) * lda + kk + c8 * 8);
            } else {
                if (bm + r < cnt) {
                    int tok = stoks[r];
                    v = *(const uint4*)(A + (size_t)tok * lda + kk + c8 * 8);
                }
            }
            rA[i] = v;
        }
        #pragma unroll
        for (int i = 0; i < WN; i++) {
            int fidx = tid + i * 256;
            int r = fidx / (NCOLS / 4), c4 = fidx % (NCOLS / 4);
            int col = bn + c4 * 4;
            float4 v1 = make_float4(0.f, 0.f, 0.f, 0.f);
            float4 v3 = v1;
            if (col < N) {
                v1 = *(const float4*)(B1 + (size_t)(kk + r) * N + col);
                v3 = *(const float4*)(B3 + (size_t)(kk + r) * N + col);
            }
            rB1[i] = v1; rB3[i] = v3;
        }
    };

    auto commit = [&](int buf) {
        #pragma unroll
        for (int i = 0; i < 2; i++) {
            int fidx = tid + i * 256;
            int r = fidx >> 2, c8 = fidx & 3;
            int slotblk = (c8 * 4) ^ swA(r);
            *(uint4*)&As32[buf][r * 16 + slotblk] = rA[i];
        }
        uint16_t* b1 = (uint16_t*)B1s32[buf];
        uint16_t* b3 = (uint16_t*)B3s32[buf];
        #pragma unroll
        for (int i = 0; i < WN; i++) {
            int fidx = tid + i * 256;
            int r = fidx / (NCOLS / 4), c4 = fidx % (NCOLS / 4);
            int sig = r >> 1, odd = r & 1;
            float w1[4] = {rB1[i].x, rB1[i].y, rB1[i].z, rB1[i].w};
            float w3[4] = {rB3[i].x, rB3[i].y, rB3[i].z, rB3[i].w};
            #pragma unroll
            for (int j = 0; j < 4; j++) {
                int col = c4 * 4 + j;
                int slot = (sig ^ swB(col)) * 2 + odd;
                f16 h1 = __float2half_rn(w1[j]);
                f16 h3 = __float2half_rn(w3[j]);
                b1[col * 32 + slot] = *(uint16_t*)&h1;
                b3[col * 32 + slot] = *(uint16_t*)&h3;
            }
        }
    };

    auto compute = [&](int buf) {
        #pragma unroll
        for (int ks = 0; ks < 2; ks++) {
            int sb = ks * 8;
            uint32_t afr[WN][4], b1fr[4][2], b3fr[4][2];
            #pragma unroll
            for (int mt = 0; mt < WN; mt++) {
                int r0 = m0w + mt * 16 + g;
                int r1 = r0 + 8;
                afr[mt][0] = As32[buf][r0 * 16 + ((sb + tg) ^ swA(r0))];
                afr[mt][1] = As32[buf][r1 * 16 + ((sb + tg) ^ swA(r1))];
                afr[mt][2] = As32[buf][r0 * 16 + ((sb + tg + 4) ^ swA(r0))];
                afr[mt][3] = As32[buf][r1 * 16 + ((sb + tg + 4) ^ swA(r1))];
            }
            #pragma unroll
            for (int nt = 0; nt < 4; nt++) {
                int c0 = n0w + nt * 8 + g;
                int sw = swB(c0);
                b1fr[nt][0] = B1s32[buf][c0 * 16 + ((sb + tg) ^ sw)];
                b1fr[nt][1] = B1s32[buf][c0 * 16 + ((sb + tg + 4) ^ sw)];
                b3fr[nt][0] = B3s32[buf][c0 * 16 + ((sb + tg) ^ sw)];
                b3fr[nt][1] = B3s32[buf][c0 * 16 + ((sb + tg + 4) ^ sw)];
            }
            #pragma unroll
            for (int mt = 0; mt < WN; mt++)
                #pragma unroll
                for (int nt = 0; nt < 4; nt++) {
                    mma_f16(acc1[mt][nt], afr[mt], b1fr[nt]);
                    mma_f16(acc3[mt][nt], afr[mt], b3fr[nt]);
                }
        }
    };

    stage(0);
    commit(0);
    if (K > 32) stage(32);
    __syncthreads();
    int buf = 0;
    for (int kk = 0; kk < K; kk += 32) {
        if (kk + 32 < K) {
            commit(buf ^ 1);
            if (kk + 64 < K) stage(kk + 64);
        }
        compute(buf);
        __syncthreads();
        buf ^= 1;
    }

    #pragma unroll
    for (int mt = 0; mt < WN; mt++) {
        #pragma unroll
        for (int half_ = 0; half_ < 2; half_++) {
            int lr = bm + m0w + mt * 16 + g + half_ * 8;
            bool rowok = (MODE == 0) ? (lr < M) : (lr < cnt);
            if (!rowok) continue;
            size_t orow = (MODE == 0) ? (size_t)lr : (size_t)(base + lr);
            #pragma unroll
            for (int nt = 0; nt < 4; nt++) {
                int col = bn + n0w + nt * 8 + 2 * tg;
                if (col >= N) continue;
                float a0 = acc1[mt][nt][half_ * 2 + 0];
                float a1 = acc1[mt][nt][half_ * 2 + 1];
                float b0 = acc3[mt][nt][half_ * 2 + 0];
                float b1 = acc3[mt][nt][half_ * 2 + 1];
                *(__half2*)(C + orow * N + col) =
                    __floats2half2_rn(silu_f(a0) * b0, silu_f(a1) * b1);
            }
        }
    }
}

// ---------------- pack per-head K ----------------
__global__ void prep_k_kernel(const f16* __restrict__ kvph, const float* __restrict__ kvF,
                              f16* __restrict__ kh) {
    long long i = (long long)blockIdx.x * 256 + threadIdx.x;
    if (i >= (long long)BH * SEQ * QK_HD) return;
    int d = (int)(i & 127);
    long long zs = i >> 7;
    int s = (int)(zs & (SEQ - 1));
    int zz = (int)(zs >> 10);
    int h = zz & 7, b = zz >> 3;
    size_t t = (size_t)b * SEQ + s;
    f16 val;
    if (d < NOPE) val = kvph[t * KVB_N + h * (NOPE + V_HD) + d];
    else          val = __float2half_rn(kvF[t * KVA_N + KV_LORA + (d - NOPE)]);
    kh[i] = val;
}

// ---------------- causal softmax ----------------
__global__ void softmax_kernel(const float* __restrict__ P, f16* __restrict__ Ph) {
    int r = blockIdx.x;
    long long zoff = (long long)blockIdx.y * SEQ * SEQ + (long long)r * SEQ;
    const float* row = P + zoff;
    f16* orow = Ph + zoff;
    int n = r + 1;
    int tid = threadIdx.x;
    float v[4];
    float m = -1e30f;
    #pragma unroll
    for (int j = 0; j < 4; j++) {
        int c = tid + j * 256;
        v[j] = (c < n) ? row[c] : -1e30f;
        m = fmaxf(m, v[j]);
    }
    m = blockReduceMax256(m);
    float e[4], l = 0.f;
    #pragma unroll
    for (int j = 0; j < 4; j++) {
        int c = tid + j * 256;
        e[j] = (c < n) ? __expf(ATTN_SCALE * (v[j] - m)) : 0.f;
        l += e[j];
    }
    l = blockReduceSum256(l);
    float inv = 1.f / l;
    #pragma unroll
    for (int j = 0; j < 4; j++) {
        int c = tid + j * 256;
        orow[c] = __float2half_rn(e[j] * inv);
    }
}

// ---------------- gate / routing ----------------
__global__ void zero_counts_kernel() {
    if (threadIdx.x < N_EXP) g_counts[threadIdx.x] = 0;
}

__global__ void gate_kernel(const float* __restrict__ xf, const float* __restrict__ gw,
                            const float* __restrict__ gb) {
    int t = blockIdx.x;
    __shared__ float sscore[N_EXP];
    int tid = threadIdx.x, warp = tid >> 5, lane = tid & 31;
    for (int e = warp; e < N_EXP; e += 4) {
        float s = 0.f;
        for (int d = lane; d < DIM; d += 32) s += xf[(size_t)t * DIM + d] * gw[(size_t)e * DIM + d];
        #pragma unroll
        for (int o = 16; o > 0; o >>= 1) s += __shfl_xor_sync(0xffffffffu, s, o);
        if (lane == 0) sscore[e] = 1.f / (1.f + expf(-s));
    }
    __syncthreads();
    if (tid == 0) {
        float orig[N_EXP], s[N_EXP];
        for (int e = 0; e < N_EXP; e++) { orig[e] = sscore[e]; s[e] = orig[e] + gb[e]; }
        float gs[N_GROUPS];
        for (int gg = 0; gg < N_GROUPS; gg++) {
            float m1 = -1e30f, m2 = -1e30f;
            for (int k = 0; k < 4; k++) {
                float v = s[gg * 4 + k];
                if (v > m1) { m2 = m1; m1 = v; } else if (v > m2) m2 = v;
            }
            gs[gg] = m1 + m2;
        }
        bool gsel[N_GROUPS] = {};
        for (int r = 0; r < TOPK_G; r++) {
            int best = -1; float bv = -1e30f;
            for (int gg = 0; gg < N_GROUPS; gg++)
                if (!gsel[gg] && gs[gg] > bv) { bv = gs[gg]; best = gg; }
            gsel[best] = true;
        }
        for (int gg = 0; gg < N_GROUPS; gg++)
            if (!gsel[gg]) for (int k = 0; k < 4; k++) s[gg * 4 + k] = -1e30f;
        int idx[TOPK]; bool used[N_EXP] = {};
        for (int r = 0; r < TOPK; r++) {
            int best = -1; float bv = -2e30f;
            for (int e = 0; e < N_EXP; e++)
                if (!used[e] && s[e] > bv) { bv = s[e]; best = e; }
            used[best] = true; idx[r] = best;
        }
        float wsum = 0.f;
        for (int r = 0; r < TOPK; r++) wsum += orig[idx[r]];
        float inv = 1.f / (wsum + 1e-20f);
        for (int r = 0; r < TOPK; r++) {
            g_expt_idx[t * TOPK + r] = idx[r];
            g_expt_w[t * TOPK + r] = orig[idx[r]] * inv;
            atomicAdd(&g_counts[idx[r]], 1);
        }
    }
}

__global__ void offsets_kernel() {
    if (threadIdx.x == 0) {
        int acc = 0;
        for (int e = 0; e < N_EXP; e++) {
            g_offsets[e] = acc;
            g_cursor[e] = acc;
            acc += g_counts[e];
        }
    }
}

__global__ void scatter_kernel() {
    int i = blockIdx.x * blockDim.x + threadIdx.x;
    if (i < NSLOT) {
        int e = g_expt_idx[i];
        int pos = atomicAdd(&g_cursor[e], 1);
        g_perm_token[pos] = i >> 2;
        g_perm_w[pos] = g_expt_w[i];
        g_slot_of[i] = pos;
    }
}

// ---------------- final combine (float4) ----------------
__global__ void final_kernel(float* __restrict__ out) {
    int t = blockIdx.x;
    int s0 = g_slot_of[t * 4 + 0], s1 = g_slot_of[t * 4 + 1];
    int s2 = g_slot_of[t * 4 + 2], s3 = g_slot_of[t * 4 + 3];
    int i = threadIdx.x;
    const float4* x2v = (const float4*)(g_x2 + (size_t)t * DIM);
    const float4* zbv = (const float4*)(g_zb + (size_t)t * DIM);
    const float4* y0 = (const float4*)(g_ybuf + (size_t)s0 * DIM);
    const float4* y1 = (const float4*)(g_ybuf + (size_t)s1 * DIM);
    const float4* y2 = (const float4*)(g_ybuf + (size_t)s2 * DIM);
    const float4* y3 = (const float4*)(g_ybuf + (size_t)s3 * DIM);
    float4 a = x2v[i], b = zbv[i], c0 = y0[i], c1 = y1[i], c2 = y2[i], c3 = y3[i];
    float4 r = make_float4(a.x + b.x + c0.x + c1.x + c2.x + c3.x,
                           a.y + b.y + c0.y + c1.y + c2.y + c3.y,
                           a.z + b.z + c0.z + c1.z + c2.z + c3.z,
                           a.w + b.w + c0.w + c1.w + c2.w + c3.w);
    *(float4*)(out + (size_t)t * DIM + i * 4) = r;
}

// ---------------- launcher ----------------
extern "C" void kernel_launch(void* const* d_in, const int* in_sizes, int n_in,
                              void* d_out, int out_size) {
    const float* x       = (const float*)d_in[0];
    const float* norm_a  = (const float*)d_in[1];
    const float* wq      = (const float*)d_in[2];
    const float* wkv_a   = (const float*)d_in[3];
    const float* kvnw    = (const float*)d_in[4];
    const float* wkv_b   = (const float*)d_in[5];
    const float* wo      = (const float*)d_in[6];
    const float* norm_m  = (const float*)d_in[7];
    const float* gate_w  = (const float*)d_in[8];
    const float* gate_b  = (const float*)d_in[9];
    const float* ew1     = (const float*)d_in[10];
    const float* ew2     = (const float*)d_in[11];
    const float* ew3     = (const float*)d_in[12];
    const float* sw1     = (const float*)d_in[13];
    const float* sw2     = (const float*)d_in[14];
    const float* sw3     = (const float*)d_in[15];
    float* out = (float*)d_out;

    float *kvF, *x2, *xf, *ybuf, *zb, *P;
    f16 *x1h, *qh, *cnh, *kvph, *khh, *Ph, *attnh, *xfh, *hbufh, *hsh;
    cudaGetSymbolAddress((void**)&kvF, g_kvF);
    cudaGetSymbolAddress((void**)&x2,  g_x2);
    cudaGetSymbolAddress((void**)&xf,  g_xf);
    cudaGetSymbolAddress((void**)&ybuf,g_ybuf);
    cudaGetSymbolAddress((void**)&zb,  g_zb);
    cudaGetSymbolAddress((void**)&P,   g_P);
    cudaGetSymbolAddress((void**)&x1h, g_x1h);
    cudaGetSymbolAddress((void**)&qh,  g_qh);
    cudaGetSymbolAddress((void**)&cnh, g_cnh);
    cudaGetSymbolAddress((void**)&kvph,g_kvph);
    cudaGetSymbolAddress((void**)&khh, g_khh);
    cudaGetSymbolAddress((void**)&Ph,  g_Ph);
    cudaGetSymbolAddress((void**)&attnh, g_attnh);
    cudaGetSymbolAddress((void**)&xfh, g_xfh);
    cudaGetSymbolAddress((void**)&hbufh, g_hbufh);
    cudaGetSymbolAddress((void**)&hsh, g_hsh);

    // 1) attention input norm -> fp16
    rmsnorm_kernel<<<TTOK, 256>>>(x, norm_a, nullptr, x1h, DIM, DIM);
    // 2) q = x1 @ wq (128x64 tiles -> 256 CTAs)
    gemm_k<0,0,true,0,2><<<dim3(16,16,1), 256>>>(x1h, wq, qh, nullptr,
        TTOK, DIM, DIM, DIM, DIM, DIM, 1, 0,0,0,0,0,0);
    // 3) kv = x1 @ wkv_a (N=320 -> 5 n-tiles of 64)
    gemm_k<0,0,false,0,2><<<dim3(5,16,1), 256>>>(x1h, wkv_a, kvF, nullptr,
        TTOK, KVA_N, DIM, DIM, KVA_N, KVA_N, 1, 0,0,0,0,0,0);
    // 4) cn = rmsnorm(kv[:, :256])
    rmsnorm_kernel<<<TTOK, 256>>>(kvF, kvnw, nullptr, cnh, KV_LORA, KVA_N);
    // 5) kvp = cn @ wkv_b
    gemm_k<0,0,true,0,2><<<dim3(24,16,1), 256>>>(cnh, wkv_b, kvph, nullptr,
        TTOK, KVB_N, KV_LORA, KV_LORA, KVB_N, KVB_N, 1, 0,0,0,0,0,0);
    // 6) pack per-head K
    prep_k_kernel<<<(int)(((long long)BH*SEQ*QK_HD + 255)/256), 256>>>(kvph, kvF, khh);
    // 7) scores = q @ kh^T, triangular 128x64 tiles (72 per z -> 1152 CTAs)
    gemm_k<0,2,false,1,2><<<dim3(72,1,BH), 256>>>(qh, khh, P, nullptr,
        SEQ, SEQ, QK_HD, DIM, QK_HD, SEQ, HEADS,
        (long long)SEQ*DIM, 128,
        (long long)HEADS*SEQ*QK_HD, (long long)SEQ*QK_HD,
        (long long)HEADS*SEQ*SEQ, (long long)SEQ*SEQ);
    // 8) causal softmax -> normalized fp16 P
    softmax_kernel<<<dim3(SEQ, BH), 256>>>(P, Ph);
    // 9) attn = P @ V, N-split 128x64 tiles (256 CTAs), causal K-limit
    gemm_k<0,1,true,2,2><<<dim3(2,8,BH), 256>>>(Ph, kvph + NOPE, attnh, nullptr,
        SEQ, V_HD, SEQ, SEQ, KVB_N, DIM, HEADS,
        (long long)HEADS*SEQ*SEQ, (long long)SEQ*SEQ,
        (long long)SEQ*KVB_N, (long long)(NOPE+V_HD),
        (long long)SEQ*DIM, 128);
    // 10) x2 = x + attn @ wo
    gemm_k<0,0,false,0,2><<<dim3(16,16,1), 256>>>(attnh, wo, x2, x,
        TTOK, DIM, DIM, DIM, DIM, DIM, 1, 0,0,0,0,0,0);
    // 11) moe input norm
    rmsnorm_kernel<<<TTOK, 256>>>(x2, norm_m, xf, xfh, DIM, DIM);
    // 12) gate + routing
    zero_counts_kernel<<<1, 32>>>();
    gate_kernel<<<TTOK, 128>>>(xf, gate_w, gate_b);
    offsets_kernel<<<1, 32>>>();
    scatter_kernel<<<NSLOT/256, 256>>>();
    // 13) routed experts: fused gated up-proj (WN=2), weighted down-proj (WN=2)
    gemm_dual<1,2><<<dim3(8,16,N_EXP), 256>>>(xfh, ew1, ew3, hbufh,
        0, INTER, DIM, DIM, (long long)DIM*INTER);
    gemm_k<2,0,false,0,2><<<dim3(16,16,N_EXP), 256>>>(hbufh, ew2, ybuf, nullptr,
        0, DIM, INTER, INTER, DIM, DIM, 1, 0,0, (long long)INTER*DIM,0, 0,0);
    // 14) shared expert: fused gated up-proj (WN=2), down-proj (WN=2)
    gemm_dual<0,2><<<dim3(8,16,1), 256>>>(xfh, sw1, sw3, hsh,
        TTOK, INTER, DIM, DIM, 0);
    gemm_k<0,0,false,0,2><<<dim3(16,16,1), 256>>>(hsh, sw2, zb, nullptr,
        TTOK, DIM, INTER, INTER, DIM, DIM, 1, 0,0,0,0,0,0);
    // 15) final combine
    final_kernel<<<TTOK, 256>>>(out);
}

// round 11
// speedup vs baseline: 1.7654x; 1.0627x over previous
#include <cuda_runtime.h>
#include <cuda_fp16.h>
#include <math.h>
#include <stdint.h>

// ---------------- problem constants ----------------
#define TTOK   2048
#define BATCH  2
#define SEQ    1024
#define DIM    1024
#define HEADS  8
#define BH     16
#define QK_HD  128
#define V_HD   128
#define NOPE   64
#define ROPE   64
#define KV_LORA 256
#define KVA_N  320
#define KVB_N  1536
#define N_EXP  32
#define N_GROUPS 8
#define TOPK   4
#define TOPK_G 4
#define INTER  512
#define NSLOT  8192
#define EPS    1e-6f
#define ATTN_SCALE 0.08838834764831843f

typedef __half f16;

// ---------------- scratch ----------------
__device__ float g_kvF [TTOK * KVA_N];
__device__ float g_x2  [TTOK * DIM];
__device__ float g_xf  [TTOK * DIM];
__device__ float g_ybuf[NSLOT * DIM];
__device__ float g_zb  [TTOK * DIM];
__device__ float g_P   [(size_t)BH * SEQ * SEQ];

__device__ f16 g_x1h [TTOK * DIM];
__device__ f16 g_qh  [TTOK * DIM];
__device__ f16 g_cnh [TTOK * KV_LORA];
__device__ f16 g_kvph[TTOK * KVB_N];
__device__ f16 g_khh [(size_t)BH * SEQ * QK_HD];
__device__ f16 g_Ph  [(size_t)BH * SEQ * SEQ];
__device__ f16 g_attnh[TTOK * DIM];
__device__ f16 g_xfh [TTOK * DIM];
__device__ f16 g_hbufh[NSLOT * INTER];
__device__ f16 g_hsh [TTOK * INTER];

__device__ int   g_counts [N_EXP];
__device__ int   g_offsets[N_EXP];
__device__ int   g_cursor [N_EXP];
__device__ int   g_expt_idx[NSLOT];
__device__ float g_expt_w [NSLOT];
__device__ int   g_perm_token[NSLOT];
__device__ float g_perm_w   [NSLOT];
__device__ int   g_slot_of  [NSLOT];

// ---------------- helpers ----------------
__device__ __forceinline__ float blockReduceSum256(float v) {
    __shared__ float red[8];
    int lane = threadIdx.x & 31, warp = threadIdx.x >> 5;
    #pragma unroll
    for (int o = 16; o > 0; o >>= 1) v += __shfl_xor_sync(0xffffffffu, v, o);
    if (lane == 0) red[warp] = v;
    __syncthreads();
    if (warp == 0) {
        v = (lane < 8) ? red[lane] : 0.f;
        #pragma unroll
        for (int o = 4; o > 0; o >>= 1) v += __shfl_xor_sync(0xffffffffu, v, o);
        if (lane == 0) red[0] = v;
    }
    __syncthreads();
    return red[0];
}

__device__ __forceinline__ float blockReduceMax256(float v) {
    __shared__ float red[8];
    int lane = threadIdx.x & 31, warp = threadIdx.x >> 5;
    #pragma unroll
    for (int o = 16; o > 0; o >>= 1) v = fmaxf(v, __shfl_xor_sync(0xffffffffu, v, o));
    if (lane == 0) red[warp] = v;
    __syncthreads();
    if (warp == 0) {
        v = (lane < 8) ? red[lane] : -1e30f;
        #pragma unroll
        for (int o = 4; o > 0; o >>= 1) v = fmaxf(v, __shfl_xor_sync(0xffffffffu, v, o));
        if (lane == 0) red[0] = v;
    }
    __syncthreads();
    return red[0];
}

__device__ __forceinline__ void mma_f16(float* c, const uint32_t* a, const uint32_t* b) {
    asm volatile(
        "mma.sync.aligned.m16n8k16.row.col.f32.f16.f16.f32 "
        "{%0,%1,%2,%3}, {%4,%5,%6,%7}, {%8,%9}, {%0,%1,%2,%3};\n"
        : "+f"(c[0]), "+f"(c[1]), "+f"(c[2]), "+f"(c[3])
        : "r"(a[0]), "r"(a[1]), "r"(a[2]), "r"(a[3]), "r"(b[0]), "r"(b[1]));
}

__device__ __forceinline__ int swA(int row) { return ((row >> 1) & 3) << 2; }
__device__ __forceinline__ int swB(int col) { return (((col >> 1) & 3) << 2) ^ ((col >> 2) & 3); }

__device__ __forceinline__ float silu_f(float a) { return a / (1.f + __expf(-a)); }

// ---------------- rmsnorm (float4 vectorized) ----------------
__global__ void rmsnorm_kernel(const float* __restrict__ x, const float* __restrict__ w,
                               float* __restrict__ o32, f16* __restrict__ o16,
                               int D, int in_stride) {
    int t = blockIdx.x;
    const float4* row = (const float4*)(x + (size_t)t * in_stride);
    const float4* wv4 = (const float4*)w;
    int nv = D >> 2;
    float ss = 0.f;
    for (int i = threadIdx.x; i < nv; i += 256) {
        float4 v = row[i];
        ss += v.x * v.x + v.y * v.y + v.z * v.z + v.w * v.w;
    }
    ss = blockReduceSum256(ss);
    __shared__ float inv;
    if (threadIdx.x == 0) inv = rsqrtf(ss / (float)D + EPS);
    __syncthreads();
    float iv = inv;
    for (int i = threadIdx.x; i < nv; i += 256) {
        float4 v = row[i];
        float4 wv = wv4[i];
        float4 r = make_float4(v.x * iv * wv.x, v.y * iv * wv.y,
                               v.z * iv * wv.z, v.w * iv * wv.w);
        if (o32) *(float4*)(o32 + (size_t)t * D + i * 4) = r;
        if (o16) {
            __half2* oh = (__half2*)(o16 + (size_t)t * D + i * 4);
            oh[0] = __floats2half2_rn(r.x, r.y);
            oh[1] = __floats2half2_rn(r.z, r.w);
        }
    }
}

// ---------------- fp16 tensor-core GEMM -----------------------------------
// CTA tile: 128 x (WN*32). 8 warps as (8/WN) x WN; per-warp WN m-subtiles x 4 n-subtiles.
// MODE 0: dense; MODE 1: A rows gathered via g_perm_token (expert z);
// MODE 2: A rows at expert offset, C scaled by g_perm_w.
// BLAY: 0 = B fp32 [K][N]; 1 = B f16 [K][N]; 2 = B f16 [N][K].
// CBF: C f16 (else fp32 + optional resid in MODE 0).
// CAUSAL: 0 none; 1 = triangular tile decode; 2 = K clipped at bm+128.
template<int MODE, int BLAY, bool CBF, int CAUSAL, int WN>
__global__ void __launch_bounds__(256)
gemm_k(const f16* __restrict__ A, const void* __restrict__ Bv, void* __restrict__ Cv,
       const float* __restrict__ resid,
       int M, int N, int K, int lda, int ldb, int ldc, int zdiv,
       long long sA1, long long sA2, long long sB1, long long sB2,
       long long sC1, long long sC2) {
    const int NCOLS = WN * 32;
    __shared__ uint32_t As32[2][2048];
    __shared__ uint32_t Bs32[2][WN * 512];
    __shared__ int stoks[128];

    int tid = threadIdx.x;
    int warp = tid >> 5, lane = tid & 31;
    int g = lane >> 2, tg = lane & 3;
    int wm = warp / WN, wn = warp % WN;
    int m0w = wm * (WN * 16), n0w = wn * 32;

    int bn, bm;
    if (CAUSAL == 1) {
        const int R = 128 / NCOLS;
        int ti = blockIdx.x;
        int bmt = 0;
        while (R * (bmt + 1) * (bmt + 2) / 2 <= ti) bmt++;
        int bnt = ti - R * bmt * (bmt + 1) / 2;
        bm = bmt * 128; bn = bnt * NCOLS;
    } else {
        bn = blockIdx.x * NCOLS;
        bm = blockIdx.y * 128;
    }
    int z = blockIdx.z;
    long long offA = (long long)(z / zdiv) * sA1 + (long long)(z % zdiv) * sA2;
    long long offB = (long long)(z / zdiv) * sB1 + (long long)(z % zdiv) * sB2;
    long long offC = (long long)(z / zdiv) * sC1 + (long long)(z % zdiv) * sC2;

    int cnt = M, base = 0;
    if (MODE != 0) {
        cnt = g_counts[z];
        base = g_offsets[z];
        if (bm >= cnt) return;
    }
    if (MODE == 1) {
        if (tid < 128) stoks[tid] = (bm + tid < cnt) ? g_perm_token[base + bm + tid] : 0;
        __syncthreads();
    }

    const f16* Ap = A + offA;
    const float* Bf = (BLAY == 0) ? ((const float*)Bv + offB) : nullptr;
    const f16*  Bh = (BLAY != 0) ? ((const f16*)Bv + offB) : nullptr;

    int Keff = K;
    if (CAUSAL == 2) { int kl = bm + 128; Keff = kl < K ? kl : K; }

    float cacc[WN][4][4];
    #pragma unroll
    for (int a = 0; a < WN; a++)
        #pragma unroll
        for (int b = 0; b < 4; b++)
            #pragma unroll
            for (int c = 0; c < 4; c++) cacc[a][b][c] = 0.f;

    uint4 rA[2];
    float4 rBf[WN];
    uint4 rBh[WN / 2];

    auto stage = [&](int kk) {
        #pragma unroll
        for (int i = 0; i < 2; i++) {
            int fidx = tid + i * 256;
            int r = fidx >> 2, c8 = fidx & 3;
            uint4 v = make_uint4(0, 0, 0, 0);
            if (MODE == 0) {
                int row = bm + r;
                if (row < M) v = *(const uint4*)(Ap + (size_t)row * lda + kk + c8 * 8);
            } else if (MODE == 1) {
                if (bm + r < cnt) {
                    int tok = stoks[r];
                    v = *(const uint4*)(Ap + (size_t)tok * lda + kk + c8 * 8);
                }
            } else {
                if (bm + r < cnt)
                    v = *(const uint4*)(Ap + (size_t)(base + bm + r) * lda + kk + c8 * 8);
            }
            rA[i] = v;
        }
        if (BLAY == 0) {
            #pragma unroll
            for (int i = 0; i < WN; i++) {
                int fidx = tid + i * 256;
                int r = fidx / (NCOLS / 4), c4 = fidx % (NCOLS / 4);
                int col = bn + c4 * 4;
                float4 v = make_float4(0.f, 0.f, 0.f, 0.f);
                if (col < N) v = *(const float4*)(Bf + (size_t)(kk + r) * ldb + col);
                rBf[i] = v;
            }
        } else if (BLAY == 1) {
            #pragma unroll
            for (int i = 0; i < WN / 2; i++) {
                int fidx = tid + i * 256;
                int r = fidx / (NCOLS / 8), c8 = fidx % (NCOLS / 8);
                int col = bn + c8 * 8;
                uint4 v = make_uint4(0, 0, 0, 0);
                if (col < N) v = *(const uint4*)(Bh + (size_t)(kk + r) * ldb + col);
                rBh[i] = v;
            }
        } else {
            #pragma unroll
            for (int i = 0; i < WN / 2; i++) {
                int fidx = tid + i * 256;
                int r = fidx >> 2, c8 = fidx & 3;
                uint4 v = make_uint4(0, 0, 0, 0);
                if (bn + r < N) v = *(const uint4*)(Bh + (size_t)(bn + r) * ldb + kk + c8 * 8);
                rBh[i] = v;
            }
        }
    };

    auto commit = [&](int buf) {
        #pragma unroll
        for (int i = 0; i < 2; i++) {
            int fidx = tid + i * 256;
            int r = fidx >> 2, c8 = fidx & 3;
            int slotblk = (c8 * 4) ^ swA(r);
            *(uint4*)&As32[buf][r * 16 + slotblk] = rA[i];
        }
        if (BLAY == 0) {
            uint16_t* Bs16 = (uint16_t*)Bs32[buf];
            #pragma unroll
            for (int i = 0; i < WN; i++) {
                int fidx = tid + i * 256;
                int r = fidx / (NCOLS / 4), c4 = fidx % (NCOLS / 4);
                int sig = r >> 1, odd = r & 1;
                float vv[4] = {rBf[i].x, rBf[i].y, rBf[i].z, rBf[i].w};
                #pragma unroll
                for (int j = 0; j < 4; j++) {
                    int col = c4 * 4 + j;
                    f16 hv = __float2half_rn(vv[j]);
                    Bs16[col * 32 + (sig ^ swB(col)) * 2 + odd] = *(uint16_t*)&hv;
                }
            }
        } else if (BLAY == 1) {
            uint16_t* Bs16 = (uint16_t*)Bs32[buf];
            #pragma unroll
            for (int i = 0; i < WN / 2; i++) {
                int fidx = tid + i * 256;
                int r = fidx / (NCOLS / 8), c8 = fidx % (NCOLS / 8);
                int sig = r >> 1, odd = r & 1;
                const uint16_t* src = (const uint16_t*)&rBh[i];
                #pragma unroll
                for (int j = 0; j < 8; j++) {
                    int col = c8 * 8 + j;
                    Bs16[col * 32 + (sig ^ swB(col)) * 2 + odd] = src[j];
                }
            }
        } else {
            #pragma unroll
            for (int i = 0; i < WN / 2; i++) {
                int fidx = tid + i * 256;
                int r = fidx >> 2, c8 = fidx & 3;
                int slotblk = (c8 * 4) ^ swA(r);
                *(uint4*)&Bs32[buf][r * 16 + slotblk] = rBh[i];
            }
        }
    };

    auto compute = [&](int buf) {
        #pragma unroll
        for (int ks = 0; ks < 2; ks++) {
            int sb = ks * 8;
            uint32_t afr[WN][4], bfr[4][2];
            #pragma unroll
            for (int mt = 0; mt < WN; mt++) {
                int r0 = m0w + mt * 16 + g;
                int r1 = r0 + 8;
                afr[mt][0] = As32[buf][r0 * 16 + ((sb + tg) ^ swA(r0))];
                afr[mt][1] = As32[buf][r1 * 16 + ((sb + tg) ^ swA(r1))];
                afr[mt][2] = As32[buf][r0 * 16 + ((sb + tg + 4) ^ swA(r0))];
                afr[mt][3] = As32[buf][r1 * 16 + ((sb + tg + 4) ^ swA(r1))];
            }
            #pragma unroll
            for (int nt = 0; nt < 4; nt++) {
                int c0 = n0w + nt * 8 + g;
                int sw = (BLAY == 2) ? swA(c0) : swB(c0);
                bfr[nt][0] = Bs32[buf][c0 * 16 + ((sb + tg) ^ sw)];
                bfr[nt][1] = Bs32[buf][c0 * 16 + ((sb + tg + 4) ^ sw)];
            }
            #pragma unroll
            for (int mt = 0; mt < WN; mt++)
                #pragma unroll
                for (int nt = 0; nt < 4; nt++)
                    mma_f16(cacc[mt][nt], afr[mt], bfr[nt]);
        }
    };

    stage(0);
    commit(0);
    if (Keff > 32) stage(32);
    __syncthreads();
    int buf = 0;
    for (int kk = 0; kk < Keff; kk += 32) {
        if (kk + 32 < Keff) {
            commit(buf ^ 1);
            if (kk + 64 < Keff) stage(kk + 64);
        }
        compute(buf);
        __syncthreads();
        buf ^= 1;
    }

    float* Cf = (float*)Cv + offC;
    f16* Ch = (f16*)Cv + offC;
    #pragma unroll
    for (int mt = 0; mt < WN; mt++) {
        #pragma unroll
        for (int half_ = 0; half_ < 2; half_++) {
            int lr = bm + m0w + mt * 16 + g + half_ * 8;
            bool rowok = (MODE == 0) ? (lr < M) : (lr < cnt);
            if (!rowok) continue;
            size_t orow = (MODE == 0) ? (size_t)lr : (size_t)(base + lr);
            float scale = (MODE == 2) ? g_perm_w[base + lr] : 1.f;
            #pragma unroll
            for (int nt = 0; nt < 4; nt++) {
                int col = bn + n0w + nt * 8 + 2 * tg;
                if (col >= N) continue;
                float v0 = cacc[mt][nt][half_ * 2 + 0];
                float v1 = cacc[mt][nt][half_ * 2 + 1];
                if (MODE == 2) { v0 *= scale; v1 *= scale; }
                if (CBF) {
                    *(__half2*)(Ch + orow * ldc + col) = __floats2half2_rn(v0, v1);
                } else {
                    if (MODE == 0 && resid) {
                        float2 rv = *(const float2*)(resid + orow * ldc + col);
                        v0 += rv.x; v1 += rv.y;
                    }
                    *(float2*)(Cf + orow * ldc + col) = make_float2(v0, v1);
                }
            }
        }
    }
}

// ---------------- fused gated up-proj: C = silu(A@B1) * (A@B3), f16 out ----
template<int MODE, int WN>
__global__ void __launch_bounds__(256)
gemm_dual(const f16* __restrict__ A, const float* __restrict__ B1g,
          const float* __restrict__ B3g, f16* __restrict__ C,
          int M, int N, int K, int lda, long long strB) {
    const int NCOLS = WN * 32;
    __shared__ uint32_t As32[2][2048];
    __shared__ uint32_t B1s32[2][WN * 512];
    __shared__ uint32_t B3s32[2][WN * 512];
    __shared__ int stoks[128];

    int tid = threadIdx.x;
    int warp = tid >> 5, lane = tid & 31;
    int g = lane >> 2, tg = lane & 3;
    int wm = warp / WN, wn = warp % WN;
    int m0w = wm * (WN * 16), n0w = wn * 32;

    int bn = blockIdx.x * NCOLS;
    int bm = blockIdx.y * 128;
    int z = blockIdx.z;

    int cnt = M, base = 0;
    if (MODE == 1) {
        cnt = g_counts[z];
        base = g_offsets[z];
        if (bm >= cnt) return;
        if (tid < 128) stoks[tid] = (bm + tid < cnt) ? g_perm_token[base + bm + tid] : 0;
        __syncthreads();
    }
    const float* B1 = B1g + (long long)z * strB;
    const float* B3 = B3g + (long long)z * strB;

    float acc1[WN][4][4], acc3[WN][4][4];
    #pragma unroll
    for (int a = 0; a < WN; a++)
        #pragma unroll
        for (int b = 0; b < 4; b++)
            #pragma unroll
            for (int c = 0; c < 4; c++) { acc1[a][b][c] = 0.f; acc3[a][b][c] = 0.f; }

    uint4 rA[2];
    float4 rB1[WN], rB3[WN];

    auto stage = [&](int kk) {
        #pragma unroll
        for (int i = 0; i < 2; i++) {
            int fidx = tid + i * 256;
            int r = fidx >> 2, c8 = fidx & 3;
            uint4 v = make_uint4(0, 0, 0, 0);
            if (MODE == 0) {
                if (bm + r < M) v = *(const uint4*)(A + (size_t)(bm + r) * lda + kk + c8 * 8);
            } else {
                if (bm + r < cnt) {
                    int tok = stoks[r];
                    v = *(const uint4*)(A + (size_t)tok * lda + kk + c8 * 8);
                }
            }
            rA[i] = v;
        }
        #pragma unroll
        for (int i = 0; i < WN; i++) {
            int fidx = tid + i * 256;
            int r = fidx / (NCOLS / 4), c4 = fidx % (NCOLS / 4);
            int col = bn + c4 * 4;
            float4 v1 = make_float4(0.f, 0.f, 0.f, 0.f);
            float4 v3 = v1;
            if (col < N) {
                v1 = *(const float4*)(B1 + (size_t)(kk + r) * N + col);
                v3 = *(const float4*)(B3 + (size_t)(kk + r) * N + col);
            }
            rB1[i] = v1; rB3[i] = v3;
        }
    };

    auto commit = [&](int buf) {
        #pragma unroll
        for (int i = 0; i < 2; i++) {
            int fidx = tid + i * 256;
            int r = fidx >> 2, c8 = fidx & 3;
            int slotblk = (c8 * 4) ^ swA(r);
            *(uint4*)&As32[buf][r * 16 + slotblk] = rA[i];
        }
        uint16_t* b1 = (uint16_t*)B1s32[buf];
        uint16_t* b3 = (uint16_t*)B3s32[buf];
        #pragma unroll
        for (int i = 0; i < WN; i++) {
            int fidx = tid + i * 256;
            int r = fidx / (NCOLS / 4), c4 = fidx % (NCOLS / 4);
            int sig = r >> 1, odd = r & 1;
            float w1[4] = {rB1[i].x, rB1[i].y, rB1[i].z, rB1[i].w};
            float w3[4] = {rB3[i].x, rB3[i].y, rB3[i].z, rB3[i].w};
            #pragma unroll
            for (int j = 0; j < 4; j++) {
                int col = c4 * 4 + j;
                int slot = (sig ^ swB(col)) * 2 + odd;
                f16 h1 = __float2half_rn(w1[j]);
                f16 h3 = __float2half_rn(w3[j]);
                b1[col * 32 + slot] = *(uint16_t*)&h1;
                b3[col * 32 + slot] = *(uint16_t*)&h3;
            }
        }
    };

    auto compute = [&](int buf) {
        #pragma unroll
        for (int ks = 0; ks < 2; ks++) {
            int sb = ks * 8;
            uint32_t afr[WN][4], b1fr[4][2], b3fr[4][2];
            #pragma unroll
            for (int mt = 0; mt < WN; mt++) {
                int r0 = m0w + mt * 16 + g;
                int r1 = r0 + 8;
                afr[mt][0] = As32[buf][r0 * 16 + ((sb + tg) ^ swA(r0))];
                afr[mt][1] = As32[buf][r1 * 16 + ((sb + tg) ^ swA(r1))];
                afr[mt][2] = As32[buf][r0 * 16 + ((sb + tg + 4) ^ swA(r0))];
                afr[mt][3] = As32[buf][r1 * 16 + ((sb + tg + 4) ^ swA(r1))];
            }
            #pragma unroll
            for (int nt = 0; nt < 4; nt++) {
                int c0 = n0w + nt * 8 + g;
                int sw = swB(c0);
                b1fr[nt][0] = B1s32[buf][c0 * 16 + ((sb + tg) ^ sw)];
                b1fr[nt][1] = B1s32[buf][c0 * 16 + ((sb + tg + 4) ^ sw)];
                b3fr[nt][0] = B3s32[buf][c0 * 16 + ((sb + tg) ^ sw)];
                b3fr[nt][1] = B3s32[buf][c0 * 16 + ((sb + tg + 4) ^ sw)];
            }
            #pragma unroll
            for (int mt = 0; mt < WN; mt++)
                #pragma unroll
                for (int nt = 0; nt < 4; nt++) {
                    mma_f16(acc1[mt][nt], afr[mt], b1fr[nt]);
                    mma_f16(acc3[mt][nt], afr[mt], b3fr[nt]);
                }
        }
    };

    stage(0);
    commit(0);
    if (K > 32) stage(32);
    __syncthreads();
    int buf = 0;
    for (int kk = 0; kk < K; kk += 32) {
        if (kk + 32 < K) {
            commit(buf ^ 1);
            if (kk + 64 < K) stage(kk + 64);
        }
        compute(buf);
        __syncthreads();
        buf ^= 1;
    }

    #pragma unroll
    for (int mt = 0; mt < WN; mt++) {
        #pragma unroll
        for (int half_ = 0; half_ < 2; half_++) {
            int lr = bm + m0w + mt * 16 + g + half_ * 8;
            bool rowok = (MODE == 0) ? (lr < M) : (lr < cnt);
            if (!rowok) continue;
            size_t orow = (MODE == 0) ? (size_t)lr : (size_t)(base + lr);
            #pragma unroll
            for (int nt = 0; nt < 4; nt++) {
                int col = bn + n0w + nt * 8 + 2 * tg;
                if (col >= N) continue;
                float a0 = acc1[mt][nt][half_ * 2 + 0];
                float a1 = acc1[mt][nt][half_ * 2 + 1];
                float b0 = acc3[mt][nt][half_ * 2 + 0];
                float b1 = acc3[mt][nt][half_ * 2 + 1];
                *(__half2*)(C + orow * N + col) =
                    __floats2half2_rn(silu_f(a0) * b0, silu_f(a1) * b1);
            }
        }
    }
}

// ---------------- pack per-head K ----------------
__global__ void prep_k_kernel(const f16* __restrict__ kvph, const float* __restrict__ kvF,
                              f16* __restrict__ kh) {
    long long i = (long long)blockIdx.x * 256 + threadIdx.x;
    if (i >= (long long)BH * SEQ * QK_HD) return;
    int d = (int)(i & 127);
    long long zs = i >> 7;
    int s = (int)(zs & (SEQ - 1));
    int zz = (int)(zs >> 10);
    int h = zz & 7, b = zz >> 3;
    size_t t = (size_t)b * SEQ + s;
    f16 val;
    if (d < NOPE) val = kvph[t * KVB_N + h * (NOPE + V_HD) + d];
    else          val = __float2half_rn(kvF[t * KVA_N + KV_LORA + (d - NOPE)]);
    kh[i] = val;
}

// ---------------- causal softmax ----------------
__global__ void softmax_kernel(const float* __restrict__ P, f16* __restrict__ Ph) {
    int r = blockIdx.x;
    long long zoff = (long long)blockIdx.y * SEQ * SEQ + (long long)r * SEQ;
    const float* row = P + zoff;
    f16* orow = Ph + zoff;
    int n = r + 1;
    int tid = threadIdx.x;
    float v[4];
    float m = -1e30f;
    #pragma unroll
    for (int j = 0; j < 4; j++) {
        int c = tid + j * 256;
        v[j] = (c < n) ? row[c] : -1e30f;
        m = fmaxf(m, v[j]);
    }
    m = blockReduceMax256(m);
    float e[4], l = 0.f;
    #pragma unroll
    for (int j = 0; j < 4; j++) {
        int c = tid + j * 256;
        e[j] = (c < n) ? __expf(ATTN_SCALE * (v[j] - m)) : 0.f;
        l += e[j];
    }
    l = blockReduceSum256(l);
    float inv = 1.f / l;
    #pragma unroll
    for (int j = 0; j < 4; j++) {
        int c = tid + j * 256;
        orow[c] = __float2half_rn(e[j] * inv);
    }
}

// ---------------- gate / routing ----------------
__global__ void zero_counts_kernel() {
    if (threadIdx.x < N_EXP) g_counts[threadIdx.x] = 0;
}

__global__ void gate_kernel(const float* __restrict__ xf, const float* __restrict__ gw,
                            const float* __restrict__ gb) {
    int t = blockIdx.x;
    __shared__ float sscore[N_EXP];
    int tid = threadIdx.x, warp = tid >> 5, lane = tid & 31;
    for (int e = warp; e < N_EXP; e += 4) {
        float s = 0.f;
        for (int d = lane; d < DIM; d += 32) s += xf[(size_t)t * DIM + d] * gw[(size_t)e * DIM + d];
        #pragma unroll
        for (int o = 16; o > 0; o >>= 1) s += __shfl_xor_sync(0xffffffffu, s, o);
        if (lane == 0) sscore[e] = 1.f / (1.f + expf(-s));
    }
    __syncthreads();
    if (tid == 0) {
        float orig[N_EXP], s[N_EXP];
        for (int e = 0; e < N_EXP; e++) { orig[e] = sscore[e]; s[e] = orig[e] + gb[e]; }
        float gs[N_GROUPS];
        for (int gg = 0; gg < N_GROUPS; gg++) {
            float m1 = -1e30f, m2 = -1e30f;
            for (int k = 0; k < 4; k++) {
                float v = s[gg * 4 + k];
                if (v > m1) { m2 = m1; m1 = v; } else if (v > m2) m2 = v;
            }
            gs[gg] = m1 + m2;
        }
        bool gsel[N_GROUPS] = {};
        for (int r = 0; r < TOPK_G; r++) {
            int best = -1; float bv = -1e30f;
            for (int gg = 0; gg < N_GROUPS; gg++)
                if (!gsel[gg] && gs[gg] > bv) { bv = gs[gg]; best = gg; }
            gsel[best] = true;
        }
        for (int gg = 0; gg < N_GROUPS; gg++)
            if (!gsel[gg]) for (int k = 0; k < 4; k++) s[gg * 4 + k] = -1e30f;
        int idx[TOPK]; bool used[N_EXP] = {};
        for (int r = 0; r < TOPK; r++) {
            int best = -1; float bv = -2e30f;
            for (int e = 0; e < N_EXP; e++)
                if (!used[e] && s[e] > bv) { bv = s[e]; best = e; }
            used[best] = true; idx[r] = best;
        }
        float wsum = 0.f;
        for (int r = 0; r < TOPK; r++) wsum += orig[idx[r]];
        float inv = 1.f / (wsum + 1e-20f);
        for (int r = 0; r < TOPK; r++) {
            g_expt_idx[t * TOPK + r] = idx[r];
            g_expt_w[t * TOPK + r] = orig[idx[r]] * inv;
            atomicAdd(&g_counts[idx[r]], 1);
        }
    }
}

__global__ void offsets_kernel() {
    if (threadIdx.x == 0) {
        int acc = 0;
        for (int e = 0; e < N_EXP; e++) {
            g_offsets[e] = acc;
            g_cursor[e] = acc;
            acc += g_counts[e];
        }
    }
}

__global__ void scatter_kernel() {
    int i = blockIdx.x * blockDim.x + threadIdx.x;
    if (i < NSLOT) {
        int e = g_expt_idx[i];
        int pos = atomicAdd(&g_cursor[e], 1);
        g_perm_token[pos] = i >> 2;
        g_perm_w[pos] = g_expt_w[i];
        g_slot_of[i] = pos;
    }
}

// ---------------- final combine (float4) ----------------
__global__ void final_kernel(float* __restrict__ out) {
    int t = blockIdx.x;
    int s0 = g_slot_of[t * 4 + 0], s1 = g_slot_of[t * 4 + 1];
    int s2 = g_slot_of[t * 4 + 2], s3 = g_slot_of[t * 4 + 3];
    int i = threadIdx.x;
    const float4* x2v = (const float4*)(g_x2 + (size_t)t * DIM);
    const float4* zbv = (const float4*)(g_zb + (size_t)t * DIM);
    const float4* y0 = (const float4*)(g_ybuf + (size_t)s0 * DIM);
    const float4* y1 = (const float4*)(g_ybuf + (size_t)s1 * DIM);
    const float4* y2 = (const float4*)(g_ybuf + (size_t)s2 * DIM);
    const float4* y3 = (const float4*)(g_ybuf + (size_t)s3 * DIM);
    float4 a = x2v[i], b = zbv[i], c0 = y0[i], c1 = y1[i], c2 = y2[i], c3 = y3[i];
    float4 r = make_float4(a.x + b.x + c0.x + c1.x + c2.x + c3.x,
                           a.y + b.y + c0.y + c1.y + c2.y + c3.y,
                           a.z + b.z + c0.z + c1.z + c2.z + c3.z,
                           a.w + b.w + c0.w + c1.w + c2.w + c3.w);
    *(float4*)(out + (size_t)t * DIM + i * 4) = r;
}

// ---------------- launcher ----------------
extern "C" void kernel_launch(void* const* d_in, const int* in_sizes, int n_in,
                              void* d_out, int out_size) {
    const float* x       = (const float*)d_in[0];
    const float* norm_a  = (const float*)d_in[1];
    const float* wq      = (const float*)d_in[2];
    const float* wkv_a   = (const float*)d_in[3];
    const float* kvnw    = (const float*)d_in[4];
    const float* wkv_b   = (const float*)d_in[5];
    const float* wo      = (const float*)d_in[6];
    const float* norm_m  = (const float*)d_in[7];
    const float* gate_w  = (const float*)d_in[8];
    const float* gate_b  = (const float*)d_in[9];
    const float* ew1     = (const float*)d_in[10];
    const float* ew2     = (const float*)d_in[11];
    const float* ew3     = (const float*)d_in[12];
    const float* sw1     = (const float*)d_in[13];
    const float* sw2     = (const float*)d_in[14];
    const float* sw3     = (const float*)d_in[15];
    float* out = (float*)d_out;

    float *kvF, *x2, *xf, *ybuf, *zb, *P;
    f16 *x1h, *qh, *cnh, *kvph, *khh, *Ph, *attnh, *xfh, *hbufh, *hsh;
    cudaGetSymbolAddress((void**)&kvF, g_kvF);
    cudaGetSymbolAddress((void**)&x2,  g_x2);
    cudaGetSymbolAddress((void**)&xf,  g_xf);
    cudaGetSymbolAddress((void**)&ybuf,g_ybuf);
    cudaGetSymbolAddress((void**)&zb,  g_zb);
    cudaGetSymbolAddress((void**)&P,   g_P);
    cudaGetSymbolAddress((void**)&x1h, g_x1h);
    cudaGetSymbolAddress((void**)&qh,  g_qh);
    cudaGetSymbolAddress((void**)&cnh, g_cnh);
    cudaGetSymbolAddress((void**)&kvph,g_kvph);
    cudaGetSymbolAddress((void**)&khh, g_khh);
    cudaGetSymbolAddress((void**)&Ph,  g_Ph);
    cudaGetSymbolAddress((void**)&attnh, g_attnh);
    cudaGetSymbolAddress((void**)&xfh, g_xfh);
    cudaGetSymbolAddress((void**)&hbufh, g_hbufh);
    cudaGetSymbolAddress((void**)&hsh, g_hsh);

    // side stream + fork/join events (created once, on the non-captured
    // correctness call; non-blocking so legacy-stream work doesn't serialize)
    static cudaStream_t s1 = nullptr;
    static cudaEvent_t evF1, evJ1, evF2, evJ2;
    if (!s1) {
        cudaStreamCreateWithFlags(&s1, cudaStreamNonBlocking);
        cudaEventCreateWithFlags(&evF1, cudaEventDisableTiming);
        cudaEventCreateWithFlags(&evJ1, cudaEventDisableTiming);
        cudaEventCreateWithFlags(&evF2, cudaEventDisableTiming);
        cudaEventCreateWithFlags(&evJ2, cudaEventDisableTiming);
    }

    // 1) attention input norm -> fp16
    rmsnorm_kernel<<<TTOK, 256>>>(x, norm_a, nullptr, x1h, DIM, DIM);

    // ---- fork 1: q-proj on s1, kv chain on main ----
    cudaEventRecord(evF1, 0);
    cudaStreamWaitEvent(s1, evF1, 0);
    // 2) q = x1 @ wq (side stream)
    gemm_k<0,0,true,0,2><<<dim3(16,16,1), 256, 0, s1>>>(x1h, wq, qh, nullptr,
        TTOK, DIM, DIM, DIM, DIM, DIM, 1, 0,0,0,0,0,0);
    // 3) kv = x1 @ wkv_a (main)
    gemm_k<0,0,false,0,2><<<dim3(5,16,1), 256>>>(x1h, wkv_a, kvF, nullptr,
        TTOK, KVA_N, DIM, DIM, KVA_N, KVA_N, 1, 0,0,0,0,0,0);
    // 4) cn = rmsnorm(kv[:, :256])
    rmsnorm_kernel<<<TTOK, 256>>>(kvF, kvnw, nullptr, cnh, KV_LORA, KVA_N);
    // 5) kvp = cn @ wkv_b
    gemm_k<0,0,true,0,2><<<dim3(24,16,1), 256>>>(cnh, wkv_b, kvph, nullptr,
        TTOK, KVB_N, KV_LORA, KV_LORA, KVB_N, KVB_N, 1, 0,0,0,0,0,0);
    // 6) pack per-head K
    prep_k_kernel<<<(int)(((long long)BH*SEQ*QK_HD + 255)/256), 256>>>(kvph, kvF, khh);
    // join q-proj back before scores
    cudaEventRecord(evJ1, s1);
    cudaStreamWaitEvent(0, evJ1, 0);

    // 7) scores = q @ kh^T, triangular 128x64 tiles
    gemm_k<0,2,false,1,2><<<dim3(72,1,BH), 256>>>(qh, khh, P, nullptr,
        SEQ, SEQ, QK_HD, DIM, QK_HD, SEQ, HEADS,
        (long long)SEQ*DIM, 128,
        (long long)HEADS*SEQ*QK_HD, (long long)SEQ*QK_HD,
        (long long)HEADS*SEQ*SEQ, (long long)SEQ*SEQ);
    // 8) causal softmax -> normalized fp16 P
    softmax_kernel<<<dim3(SEQ, BH), 256>>>(P, Ph);
    // 9) attn = P @ V, N-split 128x64 tiles, causal K-limit
    gemm_k<0,1,true,2,2><<<dim3(2,8,BH), 256>>>(Ph, kvph + NOPE, attnh, nullptr,
        SEQ, V_HD, SEQ, SEQ, KVB_N, DIM, HEADS,
        (long long)HEADS*SEQ*SEQ, (long long)SEQ*SEQ,
        (long long)SEQ*KVB_N, (long long)(NOPE+V_HD),
        (long long)SEQ*DIM, 128);
    // 10) x2 = x + attn @ wo
    gemm_k<0,0,false,0,2><<<dim3(16,16,1), 256>>>(attnh, wo, x2, x,
        TTOK, DIM, DIM, DIM, DIM, DIM, 1, 0,0,0,0,0,0);
    // 11) moe input norm
    rmsnorm_kernel<<<TTOK, 256>>>(x2, norm_m, xf, xfh, DIM, DIM);

    // ---- fork 2: shared expert on s1, routing + routed experts on main ----
    cudaEventRecord(evF2, 0);
    cudaStreamWaitEvent(s1, evF2, 0);
    // 14) shared expert (side stream)
    gemm_dual<0,2><<<dim3(8,16,1), 256, 0, s1>>>(xfh, sw1, sw3, hsh,
        TTOK, INTER, DIM, DIM, 0);
    gemm_k<0,0,false,0,2><<<dim3(16,16,1), 256, 0, s1>>>(hsh, sw2, zb, nullptr,
        TTOK, DIM, INTER, INTER, DIM, DIM, 1, 0,0,0,0,0,0);
    // 12) gate + routing (main)
    zero_counts_kernel<<<1, 32>>>();
    gate_kernel<<<TTOK, 128>>>(xf, gate_w, gate_b);
    offsets_kernel<<<1, 32>>>();
    scatter_kernel<<<NSLOT/256, 256>>>();
    // 13) routed experts
    gemm_dual<1,2><<<dim3(8,16,N_EXP), 256>>>(xfh, ew1, ew3, hbufh,
        0, INTER, DIM, DIM, (long long)DIM*INTER);
    gemm_k<2,0,false,0,2><<<dim3(16,16,N_EXP), 256>>>(hbufh, ew2, ybuf, nullptr,
        0, DIM, INTER, INTER, DIM, DIM, 1, 0,0, (long long)INTER*DIM,0, 0,0);
    // join shared expert before final
    cudaEventRecord(evJ2, s1);
    cudaStreamWaitEvent(0, evJ2, 0);

    // 15) final combine
    final_kernel<<<TTOK, 256>>>(out);
}